// round 11
// baseline (speedup 1.0000x reference)
#include <cuda_runtime.h>
#include <cuda_fp16.h>
#include <math.h>
#include <stddef.h>
#include <stdint.h>

// ---------------------------------------------------------------------------
// NeuralODE via fp16 mma.sync GEMM. CTA tile 128x128, 256 threads (8 warps,
// 64x32 warp tiles -- the R8 sweet spot), BK=32, NBUF=5, single
// __syncthreads per stage, 2 CTAs per SM. ksum carried in fp16.
// 120 GEMMs of [8192x1024]x[1024x1024]; epilogues fuse tanh / RK4 combines
// and emit the next GEMM's fp16 activations directly.
// ---------------------------------------------------------------------------

#define MDIM 8192
#define NDIM 1024
#define KDIM 1024
#define STEPS_N 10

enum EpiMode { EPI_TANH = 0, EPI_K1 = 1, EPI_KMID = 2, EPI_K4 = 3 };

constexpr int BM = 128, BN = 128, BK = 32;
constexpr int NT = 256;
constexpr int NSTAGES = KDIM / BK;  // 32
constexpr int NBUF = 5;

// smem tile: 128 rows x 32 fp16, row stride 80 B (16*5, conflict-free ldsm)
constexpr int RSB = 80;
constexpr int TILE_B = 128 * RSB;          // 10240
constexpr int T_A = 0, T_B = TILE_B;
constexpr int STAGE_B = 2 * TILE_B;        // 20480
constexpr int SMEM_TOTAL = NBUF * STAGE_B; // 102400 (2 CTAs -> 200KB/SM)

// ---- global scratch ------------------------------------------------------
__device__ float g_f32[1ull * MDIM * NDIM];           // gh (fp32 state)
__device__ unsigned short g_bf[5ull * MDIM * NDIM];   // hs, gx, y1, y2, ksum
__device__ unsigned short g_wt[3ull * KDIM * NDIM];   // w1..w3 (fp16)

// ---- PTX helpers ---------------------------------------------------------

__device__ __forceinline__ uint32_t smem_to_u32(const void* p) {
    uint32_t a;
    asm("{ .reg .u64 t; cvta.to.shared.u64 t, %1; cvt.u32.u64 %0, t; }"
        : "=r"(a) : "l"(p));
    return a;
}

#define CP_ASYNC16(saddr, gptr)                                   \
    asm volatile("cp.async.cg.shared.global [%0], [%1], 16;" ::   \
                     "r"(saddr), "l"(gptr))
#define CP_COMMIT() asm volatile("cp.async.commit_group;" ::: "memory")
#define CP_WAIT3() asm volatile("cp.async.wait_group 3;" ::: "memory")
#define CP_WAIT2() asm volatile("cp.async.wait_group 2;" ::: "memory")
#define CP_WAIT1() asm volatile("cp.async.wait_group 1;" ::: "memory")
#define CP_WAIT0() asm volatile("cp.async.wait_group 0;" ::: "memory")

#define LDSM_X4(r0, r1, r2, r3, addr)                                     \
    asm volatile("ldmatrix.sync.aligned.m8n8.x4.shared.b16 "              \
                 "{%0,%1,%2,%3}, [%4];"                                   \
                 : "=r"(r0), "=r"(r1), "=r"(r2), "=r"(r3) : "r"(addr))

#define MMA_F16(D, A, B)                                                   \
    asm volatile("mma.sync.aligned.m16n8k16.row.col.f32.f16.f16.f32 "      \
                 "{%0,%1,%2,%3}, {%4,%5,%6,%7}, {%8,%9}, {%0,%1,%2,%3};"   \
                 : "+f"((D)[0]), "+f"((D)[1]), "+f"((D)[2]), "+f"((D)[3])  \
                 : "r"((A)[0]), "r"((A)[1]), "r"((A)[2]), "r"((A)[3]),     \
                   "r"((B)[0]), "r"((B)[1]))

__device__ __forceinline__ float fast_tanh(float x) {
    float r;
    asm("tanh.approx.f32 %0, %1;" : "=f"(r) : "f"(x));
    return r;
}

__device__ __forceinline__ float4 ld4(const float* p) { return *(const float4*)p; }

__device__ __forceinline__ uint32_t pack_h2(float a, float b) {
    __half2 h = __floats2half2_rn(a, b);
    return *(uint32_t*)&h;
}

__device__ __forceinline__ float2 unpack_h2(uint32_t u) {
    __half2 h = *(__half2*)&u;
    return __half22float2(h);
}

// ---- weight convert+transpose: out[n][k] = fp16(W[k][n]) -----------------

__global__ void wsplit_kernel(const float* __restrict__ W,
                              unsigned short* __restrict__ hi) {
    __shared__ float t[32][33];
    const int tx = threadIdx.x, ty = threadIdx.y;
    const int n0 = blockIdx.x * 32, k0 = blockIdx.y * 32;
#pragma unroll
    for (int j = 0; j < 32; j += 8)
        t[ty + j][tx] = W[(size_t)(k0 + ty + j) * NDIM + n0 + tx];
    __syncthreads();
#pragma unroll
    for (int j = 0; j < 32; j += 8) {
        float v = t[tx][ty + j];
        __half h = __float2half_rn(v);
        hi[(size_t)(n0 + ty + j) * KDIM + k0 + tx] = *(unsigned short*)&h;
    }
}

// ---- activation convert (h0 prologue) ------------------------------------

__global__ void asplit_kernel(const float* __restrict__ X,
                              unsigned short* __restrict__ hi) {
    size_t i = ((size_t)blockIdx.x * blockDim.x + threadIdx.x) * 4;
    float4 v = ld4(X + i);
    *(uint2*)(hi + i) = make_uint2(pack_h2(v.x, v.y), pack_h2(v.z, v.w));
}

// ---- fused epilogue per (row, col-pair) ----------------------------------
// ksum is fp16 (packed half2). hbase stays fp32.

template <int EPI>
__device__ __forceinline__ void epi_rc(int m, int c, float v0, float v1,
                                       unsigned short* oh,
                                       const float* hbase,
                                       unsigned short* ksum,
                                       float* hout, float coef) {
    const size_t idx = (size_t)m * NDIM + c;
    if (EPI == EPI_TANH) {
        *(uint32_t*)(oh + idx) = pack_h2(fast_tanh(v0), fast_tanh(v1));
    } else if (EPI == EPI_K1) {
        *(uint32_t*)(ksum + idx) = pack_h2(v0, v1);
        float2 h = *(const float2*)(hbase + idx);
        *(uint32_t*)(oh + idx) =
            pack_h2(fmaf(coef, v0, h.x), fmaf(coef, v1, h.y));
    } else if (EPI == EPI_KMID) {
        float2 s = unpack_h2(*(uint32_t*)(ksum + idx));
        s.x = fmaf(2.f, v0, s.x);
        s.y = fmaf(2.f, v1, s.y);
        *(uint32_t*)(ksum + idx) = pack_h2(s.x, s.y);
        float2 h = *(const float2*)(hbase + idx);
        *(uint32_t*)(oh + idx) =
            pack_h2(fmaf(coef, v0, h.x), fmaf(coef, v1, h.y));
    } else {  // EPI_K4
        float2 s = unpack_h2(*(uint32_t*)(ksum + idx));
        float2 h = *(const float2*)(hbase + idx);
        float g0 = fmaf(coef, s.x + v0, h.x);
        float g1 = fmaf(coef, s.y + v1, h.y);
        *(float2*)(hout + idx) = make_float2(g0, g1);
        *(uint32_t*)(oh + idx) = pack_h2(g0, g1);
    }
}

// ---- main GEMM -----------------------------------------------------------

template <int EPI>
__global__ void __launch_bounds__(NT, 2)
ngemm_kernel(const unsigned short* __restrict__ Ax,
             const unsigned short* __restrict__ Bx,
             const float* __restrict__ bias,
             const float* __restrict__ trow, float tval,
             unsigned short* __restrict__ oh,
             const float* __restrict__ hbase,
             unsigned short* __restrict__ ksum,
             float* __restrict__ hout, float coef) {
    extern __shared__ char smc[];
    const uint32_t sb = smem_to_u32(smc);
    const int tid = threadIdx.x;
    const int lane = tid & 31;
    const int w = tid >> 5;
    const int wm = w & 1;        // 2 x 64 rows
    const int wn = w >> 1;       // 4 x 32 cols
    const int bm = blockIdx.y * BM;
    const int bn = blockIdx.x * BN;

    // cp.async chunk mapping: 512 x 16B chunks per tile, 2 per thread
    const int ch0 = tid, ch1 = tid + NT;
    const int r0 = ch0 >> 2, e0 = (ch0 & 3) * 8;
    const int r1 = ch1 >> 2, e1 = (ch1 & 3) * 8;
    const unsigned short* ga0 = Ax + (size_t)(bm + r0) * KDIM + e0;
    const unsigned short* ga1 = Ax + (size_t)(bm + r1) * KDIM + e1;
    const unsigned short* gb0 = Bx + (size_t)(bn + r0) * KDIM + e0;
    const unsigned short* gb1 = Bx + (size_t)(bn + r1) * KDIM + e1;
    const uint32_t s0 = (uint32_t)(r0 * RSB + (ch0 & 3) * 16);
    const uint32_t s1 = (uint32_t)(r1 * RSB + (ch1 & 3) * 16);

    const uint32_t a_off = (uint32_t)((lane & 15) * RSB + ((lane & 16) ? 16 : 0));
    const uint32_t b_off = (uint32_t)(((lane & 7) + ((lane & 16) ? 8 : 0)) * RSB +
                                      ((lane & 8) ? 16 : 0));

    float acc[4][4][4];
#pragma unroll
    for (int i = 0; i < 4; i++)
#pragma unroll
        for (int j = 0; j < 4; j++)
#pragma unroll
            for (int q = 0; q < 4; q++) acc[i][j][q] = 0.f;

#define ISSUE_STAGE(st)                                                   \
    do {                                                                  \
        const int _kc = (st) * BK;                                        \
        const uint32_t _b = sb + ((st) % NBUF) * STAGE_B;                 \
        CP_ASYNC16(_b + T_A + s0, ga0 + _kc);                             \
        CP_ASYNC16(_b + T_A + s1, ga1 + _kc);                             \
        CP_ASYNC16(_b + T_B + s0, gb0 + _kc);                             \
        CP_ASYNC16(_b + T_B + s1, gb1 + _kc);                             \
        CP_COMMIT();                                                      \
    } while (0)

    ISSUE_STAGE(0);
    ISSUE_STAGE(1);
    ISSUE_STAGE(2);
    ISSUE_STAGE(3);

#pragma unroll 1
    for (int s = 0; s < NSTAGES; ++s) {
        // Ensure group s complete; pending is a subset of {s .. s+3}
        // (ISSUE(s+4) happens after the barrier below).
        if (s + 3 < NSTAGES) {
            CP_WAIT3();
        } else if (s + 2 < NSTAGES) {
            CP_WAIT2();
        } else if (s + 1 < NSTAGES) {
            CP_WAIT1();
        } else {
            CP_WAIT0();
        }
        // Single barrier: stage-s data visible to all warps AND buffer
        // (s-1)%NBUF fully consumed (read in stage s-1, before this
        // barrier), so ISSUE(s+4) may overwrite it.
        __syncthreads();
        if (s + 4 < NSTAGES) ISSUE_STAGE(s + 4);

        const uint32_t base = sb + (s % NBUF) * STAGE_B;
#pragma unroll
        for (int ks = 0; ks < 2; ++ks) {
            uint32_t a_[4][4], b_[4][2];
#pragma unroll
            for (int i = 0; i < 4; ++i) {
                const uint32_t ra =
                    base + (uint32_t)((wm * 64 + i * 16) * RSB + ks * 32) + a_off;
                LDSM_X4(a_[i][0], a_[i][1], a_[i][2], a_[i][3], ra + T_A);
            }
#pragma unroll
            for (int jj = 0; jj < 2; ++jj) {
                const uint32_t rb =
                    base + (uint32_t)((wn * 32 + jj * 16) * RSB + ks * 32) + b_off;
                uint32_t t0, t1, t2, t3;
                LDSM_X4(t0, t1, t2, t3, rb + T_B);
                b_[2 * jj][0] = t0; b_[2 * jj][1] = t1;
                b_[2 * jj + 1][0] = t2; b_[2 * jj + 1][1] = t3;
            }
#pragma unroll
            for (int i = 0; i < 4; ++i)
#pragma unroll
                for (int j = 0; j < 4; ++j) {
                    MMA_F16(acc[i][j], a_[i], b_[j]);
                }
        }
    }
#undef ISSUE_STAGE

    // ---------------- epilogue -------------------------------------------
#pragma unroll
    for (int j = 0; j < 4; ++j) {
        const int c = bn + wn * 32 + j * 8 + (lane & 3) * 2;
        float bb0 = bias[c], bb1 = bias[c + 1];
        if (EPI == EPI_TANH && trow != nullptr) {
            bb0 = fmaf(tval, trow[c], bb0);
            bb1 = fmaf(tval, trow[c + 1], bb1);
        }
#pragma unroll
        for (int i = 0; i < 4; ++i) {
            const int m0 = bm + wm * 64 + i * 16 + (lane >> 2);
            epi_rc<EPI>(m0, c, acc[i][j][0] + bb0, acc[i][j][1] + bb1,
                        oh, hbase, ksum, hout, coef);
            epi_rc<EPI>(m0 + 8, c, acc[i][j][2] + bb0, acc[i][j][3] + bb1,
                        oh, hbase, ksum, hout, coef);
        }
    }
}

// ---------------------------------------------------------------------------

template <int EPI>
static inline void launch_gemm(const unsigned short* Ax, const unsigned short* Bx,
                               const float* bias, const float* trow, float tval,
                               unsigned short* oh, const float* hbase,
                               unsigned short* ksum, float* hout, float coef) {
    dim3 grid(NDIM / BN, MDIM / BM);
    ngemm_kernel<EPI><<<grid, NT, SMEM_TOTAL>>>(Ax, Bx, bias, trow, tval,
                                                oh, hbase, ksum, hout, coef);
}

extern "C" void kernel_launch(void* const* d_in, const int* in_sizes, int n_in,
                              void* d_out, int out_size) {
    const float* h0 = (const float*)d_in[0];
    const float* W1 = (const float*)d_in[1];
    const float* b1 = (const float*)d_in[2];
    const float* W2 = (const float*)d_in[3];
    const float* b2 = (const float*)d_in[4];
    const float* W3 = (const float*)d_in[5];
    const float* b3 = (const float*)d_in[6];
    float* out = (float*)d_out;

    cudaFuncSetAttribute(ngemm_kernel<EPI_TANH>,
                         cudaFuncAttributeMaxDynamicSharedMemorySize, SMEM_TOTAL);
    cudaFuncSetAttribute(ngemm_kernel<EPI_K1>,
                         cudaFuncAttributeMaxDynamicSharedMemorySize, SMEM_TOTAL);
    cudaFuncSetAttribute(ngemm_kernel<EPI_KMID>,
                         cudaFuncAttributeMaxDynamicSharedMemorySize, SMEM_TOTAL);
    cudaFuncSetAttribute(ngemm_kernel<EPI_K4>,
                         cudaFuncAttributeMaxDynamicSharedMemorySize, SMEM_TOTAL);

    float* fbase = nullptr;
    cudaGetSymbolAddress((void**)&fbase, g_f32);
    unsigned short* abase = nullptr;
    cudaGetSymbolAddress((void**)&abase, g_bf);
    unsigned short* wbase = nullptr;
    cudaGetSymbolAddress((void**)&wbase, g_wt);

    const size_t SZ = (size_t)MDIM * NDIM;
    float* gh = fbase;                     // carried fp32 state

    unsigned short* hs = abase;            // h as fp16
    unsigned short* gx = abase + SZ;       // dynamics input fp16
    unsigned short* y1 = abase + 2 * SZ;
    unsigned short* y2 = abase + 3 * SZ;
    unsigned short* ks = abase + 4 * SZ;   // ksum fp16

    const size_t WSZ = (size_t)KDIM * NDIM;
    unsigned short* w1x = wbase;
    unsigned short* w2x = wbase + WSZ;
    unsigned short* w3x = wbase + 2 * WSZ;

    {
        dim3 g(NDIM / 32, KDIM / 32), b(32, 8);
        wsplit_kernel<<<g, b>>>(W1, w1x);
        wsplit_kernel<<<g, b>>>(W2, w2x);
        wsplit_kernel<<<g, b>>>(W3, w3x);
        asplit_kernel<<<(int)(SZ / 4 / 256), 256>>>(h0, hs);
    }

    const float dt = 0.1f;
    const float* trow = W1 + (size_t)KDIM * NDIM;  // W1 row 1024 (t row)

    for (int s = 0; s < STEPS_N; s++) {
        const float t0 = dt * (float)s;
        const float* hin = (s == 0) ? h0 : gh;
        float* hdst = (s == STEPS_N - 1) ? out : gh;

        // k1 = f(t0, h)
        launch_gemm<EPI_TANH>(hs, w1x, b1, trow, t0, y1, nullptr, nullptr, nullptr, 0.f);
        launch_gemm<EPI_TANH>(y1, w2x, b2, nullptr, 0.f, y2, nullptr, nullptr, nullptr, 0.f);
        launch_gemm<EPI_K1>(y2, w3x, b3, nullptr, 0.f, gx, hin, ks, nullptr, dt * 0.5f);
        // k2
        launch_gemm<EPI_TANH>(gx, w1x, b1, trow, t0 + dt * 0.5f, y1, nullptr, nullptr, nullptr, 0.f);
        launch_gemm<EPI_TANH>(y1, w2x, b2, nullptr, 0.f, y2, nullptr, nullptr, nullptr, 0.f);
        launch_gemm<EPI_KMID>(y2, w3x, b3, nullptr, 0.f, gx, hin, ks, nullptr, dt * 0.5f);
        // k3
        launch_gemm<EPI_TANH>(gx, w1x, b1, trow, t0 + dt * 0.5f, y1, nullptr, nullptr, nullptr, 0.f);
        launch_gemm<EPI_TANH>(y1, w2x, b2, nullptr, 0.f, y2, nullptr, nullptr, nullptr, 0.f);
        launch_gemm<EPI_KMID>(y2, w3x, b3, nullptr, 0.f, gx, hin, ks, nullptr, dt);
        // k4 + combine
        launch_gemm<EPI_TANH>(gx, w1x, b1, trow, t0 + dt, y1, nullptr, nullptr, nullptr, 0.f);
        launch_gemm<EPI_TANH>(y1, w2x, b2, nullptr, 0.f, y2, nullptr, nullptr, nullptr, 0.f);
        launch_gemm<EPI_K4>(y2, w3x, b3, nullptr, 0.f, hs, hin, ks, hdst, dt / 6.0f);
    }
}

// round 12
// speedup vs baseline: 1.0448x; 1.0448x over previous
#include <cuda_runtime.h>
#include <cuda_fp16.h>
#include <math.h>
#include <stddef.h>
#include <stdint.h>

// ---------------------------------------------------------------------------
// NeuralODE via fp16 mma.sync GEMM. CTA tile 128x128, 256 threads (8 warps,
// 64x32 warp tiles), BK=32, NBUF=4 (the R8 verified-best pipeline), single
// __syncthreads per stage, 2 CTAs per SM. ksum fp16; K1/KMID read h as fp16.
// 120 GEMMs of [8192x1024]x[1024x1024]; epilogues fuse tanh / RK4 combines
// and emit the next GEMM's fp16 activations directly.
// ---------------------------------------------------------------------------

#define MDIM 8192
#define NDIM 1024
#define KDIM 1024
#define STEPS_N 10

enum EpiMode { EPI_TANH = 0, EPI_K1 = 1, EPI_KMID = 2, EPI_K4 = 3 };

constexpr int BM = 128, BN = 128, BK = 32;
constexpr int NT = 256;
constexpr int NSTAGES = KDIM / BK;  // 32
constexpr int NBUF = 4;

// smem tile: 128 rows x 32 fp16, row stride 80 B (16*5, conflict-free ldsm)
constexpr int RSB = 80;
constexpr int TILE_B = 128 * RSB;          // 10240
constexpr int T_A = 0, T_B = TILE_B;
constexpr int STAGE_B = 2 * TILE_B;        // 20480
constexpr int SMEM_TOTAL = NBUF * STAGE_B; // 81920 (2 CTAs -> 160KB/SM)

// ---- global scratch ------------------------------------------------------
__device__ float g_f32[1ull * MDIM * NDIM];           // gh (fp32 state)
__device__ unsigned short g_bf[5ull * MDIM * NDIM];   // hs, gx, y1, y2, ksum
__device__ unsigned short g_wt[3ull * KDIM * NDIM];   // w1..w3 (fp16)

// ---- PTX helpers ---------------------------------------------------------

__device__ __forceinline__ uint32_t smem_to_u32(const void* p) {
    uint32_t a;
    asm("{ .reg .u64 t; cvta.to.shared.u64 t, %1; cvt.u32.u64 %0, t; }"
        : "=r"(a) : "l"(p));
    return a;
}

#define CP_ASYNC16(saddr, gptr)                                   \
    asm volatile("cp.async.cg.shared.global [%0], [%1], 16;" ::   \
                     "r"(saddr), "l"(gptr))
#define CP_COMMIT() asm volatile("cp.async.commit_group;" ::: "memory")
#define CP_WAIT2() asm volatile("cp.async.wait_group 2;" ::: "memory")
#define CP_WAIT1() asm volatile("cp.async.wait_group 1;" ::: "memory")
#define CP_WAIT0() asm volatile("cp.async.wait_group 0;" ::: "memory")

#define LDSM_X4(r0, r1, r2, r3, addr)                                     \
    asm volatile("ldmatrix.sync.aligned.m8n8.x4.shared.b16 "              \
                 "{%0,%1,%2,%3}, [%4];"                                   \
                 : "=r"(r0), "=r"(r1), "=r"(r2), "=r"(r3) : "r"(addr))

#define MMA_F16(D, A, B)                                                   \
    asm volatile("mma.sync.aligned.m16n8k16.row.col.f32.f16.f16.f32 "      \
                 "{%0,%1,%2,%3}, {%4,%5,%6,%7}, {%8,%9}, {%0,%1,%2,%3};"   \
                 : "+f"((D)[0]), "+f"((D)[1]), "+f"((D)[2]), "+f"((D)[3])  \
                 : "r"((A)[0]), "r"((A)[1]), "r"((A)[2]), "r"((A)[3]),     \
                   "r"((B)[0]), "r"((B)[1]))

__device__ __forceinline__ float fast_tanh(float x) {
    float r;
    asm("tanh.approx.f32 %0, %1;" : "=f"(r) : "f"(x));
    return r;
}

__device__ __forceinline__ float4 ld4(const float* p) { return *(const float4*)p; }

__device__ __forceinline__ uint32_t pack_h2(float a, float b) {
    __half2 h = __floats2half2_rn(a, b);
    return *(uint32_t*)&h;
}

__device__ __forceinline__ float2 unpack_h2(uint32_t u) {
    __half2 h = *(__half2*)&u;
    return __half22float2(h);
}

// ---- weight convert+transpose: out[n][k] = fp16(W[k][n]) -----------------

__global__ void wsplit_kernel(const float* __restrict__ W,
                              unsigned short* __restrict__ hi) {
    __shared__ float t[32][33];
    const int tx = threadIdx.x, ty = threadIdx.y;
    const int n0 = blockIdx.x * 32, k0 = blockIdx.y * 32;
#pragma unroll
    for (int j = 0; j < 32; j += 8)
        t[ty + j][tx] = W[(size_t)(k0 + ty + j) * NDIM + n0 + tx];
    __syncthreads();
#pragma unroll
    for (int j = 0; j < 32; j += 8) {
        float v = t[tx][ty + j];
        __half h = __float2half_rn(v);
        hi[(size_t)(n0 + ty + j) * KDIM + k0 + tx] = *(unsigned short*)&h;
    }
}

// ---- activation convert (h0 prologue) ------------------------------------

__global__ void asplit_kernel(const float* __restrict__ X,
                              unsigned short* __restrict__ hi) {
    size_t i = ((size_t)blockIdx.x * blockDim.x + threadIdx.x) * 4;
    float4 v = ld4(X + i);
    *(uint2*)(hi + i) = make_uint2(pack_h2(v.x, v.y), pack_h2(v.z, v.w));
}

// ---- fused epilogue per (row, col-pair) ----------------------------------
// ksum fp16. K1/KMID read h via hb16 (fp16); K4 reads fp32 hbase.

template <int EPI>
__device__ __forceinline__ void epi_rc(int m, int c, float v0, float v1,
                                       unsigned short* oh,
                                       const float* hbase,
                                       const unsigned short* hb16,
                                       unsigned short* ksum,
                                       float* hout, float coef) {
    const size_t idx = (size_t)m * NDIM + c;
    if (EPI == EPI_TANH) {
        *(uint32_t*)(oh + idx) = pack_h2(fast_tanh(v0), fast_tanh(v1));
    } else if (EPI == EPI_K1) {
        *(uint32_t*)(ksum + idx) = pack_h2(v0, v1);
        float2 h = unpack_h2(*(const uint32_t*)(hb16 + idx));
        *(uint32_t*)(oh + idx) =
            pack_h2(fmaf(coef, v0, h.x), fmaf(coef, v1, h.y));
    } else if (EPI == EPI_KMID) {
        float2 s = unpack_h2(*(uint32_t*)(ksum + idx));
        s.x = fmaf(2.f, v0, s.x);
        s.y = fmaf(2.f, v1, s.y);
        *(uint32_t*)(ksum + idx) = pack_h2(s.x, s.y);
        float2 h = unpack_h2(*(const uint32_t*)(hb16 + idx));
        *(uint32_t*)(oh + idx) =
            pack_h2(fmaf(coef, v0, h.x), fmaf(coef, v1, h.y));
    } else {  // EPI_K4: oh = hs snapshot for next step (fp16), hout fp32
        float2 s = unpack_h2(*(uint32_t*)(ksum + idx));
        float2 h = *(const float2*)(hbase + idx);
        float g0 = fmaf(coef, s.x + v0, h.x);
        float g1 = fmaf(coef, s.y + v1, h.y);
        *(float2*)(hout + idx) = make_float2(g0, g1);
        *(uint32_t*)(oh + idx) = pack_h2(g0, g1);
    }
}

// ---- main GEMM -----------------------------------------------------------

template <int EPI>
__global__ void __launch_bounds__(NT, 2)
ngemm_kernel(const unsigned short* __restrict__ Ax,
             const unsigned short* __restrict__ Bx,
             const float* __restrict__ bias,
             const float* __restrict__ trow, float tval,
             unsigned short* __restrict__ oh,
             const float* __restrict__ hbase,
             const unsigned short* __restrict__ hb16,
             unsigned short* __restrict__ ksum,
             float* __restrict__ hout, float coef) {
    extern __shared__ char smc[];
    const uint32_t sb = smem_to_u32(smc);
    const int tid = threadIdx.x;
    const int lane = tid & 31;
    const int w = tid >> 5;
    const int wm = w & 1;        // 2 x 64 rows
    const int wn = w >> 1;       // 4 x 32 cols
    const int bm = blockIdx.y * BM;
    const int bn = blockIdx.x * BN;

    // cp.async chunk mapping: 512 x 16B chunks per tile, 2 per thread
    const int ch0 = tid, ch1 = tid + NT;
    const int r0 = ch0 >> 2, e0 = (ch0 & 3) * 8;
    const int r1 = ch1 >> 2, e1 = (ch1 & 3) * 8;
    const unsigned short* ga0 = Ax + (size_t)(bm + r0) * KDIM + e0;
    const unsigned short* ga1 = Ax + (size_t)(bm + r1) * KDIM + e1;
    const unsigned short* gb0 = Bx + (size_t)(bn + r0) * KDIM + e0;
    const unsigned short* gb1 = Bx + (size_t)(bn + r1) * KDIM + e1;
    const uint32_t s0 = (uint32_t)(r0 * RSB + (ch0 & 3) * 16);
    const uint32_t s1 = (uint32_t)(r1 * RSB + (ch1 & 3) * 16);

    const uint32_t a_off = (uint32_t)((lane & 15) * RSB + ((lane & 16) ? 16 : 0));
    const uint32_t b_off = (uint32_t)(((lane & 7) + ((lane & 16) ? 8 : 0)) * RSB +
                                      ((lane & 8) ? 16 : 0));

    float acc[4][4][4];
#pragma unroll
    for (int i = 0; i < 4; i++)
#pragma unroll
        for (int j = 0; j < 4; j++)
#pragma unroll
            for (int q = 0; q < 4; q++) acc[i][j][q] = 0.f;

#define ISSUE_STAGE(st)                                                   \
    do {                                                                  \
        const int _kc = (st) * BK;                                        \
        const uint32_t _b = sb + ((st) % NBUF) * STAGE_B;                 \
        CP_ASYNC16(_b + T_A + s0, ga0 + _kc);                             \
        CP_ASYNC16(_b + T_A + s1, ga1 + _kc);                             \
        CP_ASYNC16(_b + T_B + s0, gb0 + _kc);                             \
        CP_ASYNC16(_b + T_B + s1, gb1 + _kc);                             \
        CP_COMMIT();                                                      \
    } while (0)

    ISSUE_STAGE(0);
    ISSUE_STAGE(1);
    ISSUE_STAGE(2);

#pragma unroll 1
    for (int s = 0; s < NSTAGES; ++s) {
        if (s + 2 < NSTAGES) {
            CP_WAIT2();
        } else if (s + 1 < NSTAGES) {
            CP_WAIT1();
        } else {
            CP_WAIT0();
        }
        __syncthreads();
        if (s + 3 < NSTAGES) ISSUE_STAGE(s + 3);

        const uint32_t base = sb + (s % NBUF) * STAGE_B;
#pragma unroll
        for (int ks = 0; ks < 2; ++ks) {
            uint32_t a_[4][4], b_[4][2];
#pragma unroll
            for (int i = 0; i < 4; ++i) {
                const uint32_t ra =
                    base + (uint32_t)((wm * 64 + i * 16) * RSB + ks * 32) + a_off;
                LDSM_X4(a_[i][0], a_[i][1], a_[i][2], a_[i][3], ra + T_A);
            }
#pragma unroll
            for (int jj = 0; jj < 2; ++jj) {
                const uint32_t rb =
                    base + (uint32_t)((wn * 32 + jj * 16) * RSB + ks * 32) + b_off;
                uint32_t t0, t1, t2, t3;
                LDSM_X4(t0, t1, t2, t3, rb + T_B);
                b_[2 * jj][0] = t0; b_[2 * jj][1] = t1;
                b_[2 * jj + 1][0] = t2; b_[2 * jj + 1][1] = t3;
            }
#pragma unroll
            for (int i = 0; i < 4; ++i)
#pragma unroll
                for (int j = 0; j < 4; ++j) {
                    MMA_F16(acc[i][j], a_[i], b_[j]);
                }
        }
    }
#undef ISSUE_STAGE

    // ---------------- epilogue -------------------------------------------
#pragma unroll
    for (int j = 0; j < 4; ++j) {
        const int c = bn + wn * 32 + j * 8 + (lane & 3) * 2;
        float bb0 = bias[c], bb1 = bias[c + 1];
        if (EPI == EPI_TANH && trow != nullptr) {
            bb0 = fmaf(tval, trow[c], bb0);
            bb1 = fmaf(tval, trow[c + 1], bb1);
        }
#pragma unroll
        for (int i = 0; i < 4; ++i) {
            const int m0 = bm + wm * 64 + i * 16 + (lane >> 2);
            epi_rc<EPI>(m0, c, acc[i][j][0] + bb0, acc[i][j][1] + bb1,
                        oh, hbase, hb16, ksum, hout, coef);
            epi_rc<EPI>(m0 + 8, c, acc[i][j][2] + bb0, acc[i][j][3] + bb1,
                        oh, hbase, hb16, ksum, hout, coef);
        }
    }
}

// ---------------------------------------------------------------------------

template <int EPI>
static inline void launch_gemm(const unsigned short* Ax, const unsigned short* Bx,
                               const float* bias, const float* trow, float tval,
                               unsigned short* oh, const float* hbase,
                               const unsigned short* hb16,
                               unsigned short* ksum, float* hout, float coef) {
    dim3 grid(NDIM / BN, MDIM / BM);
    ngemm_kernel<EPI><<<grid, NT, SMEM_TOTAL>>>(Ax, Bx, bias, trow, tval,
                                                oh, hbase, hb16, ksum, hout,
                                                coef);
}

extern "C" void kernel_launch(void* const* d_in, const int* in_sizes, int n_in,
                              void* d_out, int out_size) {
    const float* h0 = (const float*)d_in[0];
    const float* W1 = (const float*)d_in[1];
    const float* b1 = (const float*)d_in[2];
    const float* W2 = (const float*)d_in[3];
    const float* b2 = (const float*)d_in[4];
    const float* W3 = (const float*)d_in[5];
    const float* b3 = (const float*)d_in[6];
    float* out = (float*)d_out;

    cudaFuncSetAttribute(ngemm_kernel<EPI_TANH>,
                         cudaFuncAttributeMaxDynamicSharedMemorySize, SMEM_TOTAL);
    cudaFuncSetAttribute(ngemm_kernel<EPI_K1>,
                         cudaFuncAttributeMaxDynamicSharedMemorySize, SMEM_TOTAL);
    cudaFuncSetAttribute(ngemm_kernel<EPI_KMID>,
                         cudaFuncAttributeMaxDynamicSharedMemorySize, SMEM_TOTAL);
    cudaFuncSetAttribute(ngemm_kernel<EPI_K4>,
                         cudaFuncAttributeMaxDynamicSharedMemorySize, SMEM_TOTAL);

    float* fbase = nullptr;
    cudaGetSymbolAddress((void**)&fbase, g_f32);
    unsigned short* abase = nullptr;
    cudaGetSymbolAddress((void**)&abase, g_bf);
    unsigned short* wbase = nullptr;
    cudaGetSymbolAddress((void**)&wbase, g_wt);

    const size_t SZ = (size_t)MDIM * NDIM;
    float* gh = fbase;                     // carried fp32 state

    unsigned short* hs = abase;            // fp16 snapshot of step-start h
    unsigned short* gx = abase + SZ;       // dynamics input fp16
    unsigned short* y1 = abase + 2 * SZ;
    unsigned short* y2 = abase + 3 * SZ;
    unsigned short* ks = abase + 4 * SZ;   // ksum fp16

    const size_t WSZ = (size_t)KDIM * NDIM;
    unsigned short* w1x = wbase;
    unsigned short* w2x = wbase + WSZ;
    unsigned short* w3x = wbase + 2 * WSZ;

    {
        dim3 g(NDIM / 32, KDIM / 32), b(32, 8);
        wsplit_kernel<<<g, b>>>(W1, w1x);
        wsplit_kernel<<<g, b>>>(W2, w2x);
        wsplit_kernel<<<g, b>>>(W3, w3x);
        asplit_kernel<<<(int)(SZ / 4 / 256), 256>>>(h0, hs);
    }

    const float dt = 0.1f;
    const float* trow = W1 + (size_t)KDIM * NDIM;  // W1 row 1024 (t row)

    for (int s = 0; s < STEPS_N; s++) {
        const float t0 = dt * (float)s;
        const float* hin = (s == 0) ? h0 : gh;
        float* hdst = (s == STEPS_N - 1) ? out : gh;

        // k1 = f(t0, h)
        launch_gemm<EPI_TANH>(hs, w1x, b1, trow, t0, y1, nullptr, nullptr, nullptr, nullptr, 0.f);
        launch_gemm<EPI_TANH>(y1, w2x, b2, nullptr, 0.f, y2, nullptr, nullptr, nullptr, nullptr, 0.f);
        launch_gemm<EPI_K1>(y2, w3x, b3, nullptr, 0.f, gx, nullptr, hs, ks, nullptr, dt * 0.5f);
        // k2 = f(t0+dt/2, h + dt/2*k1)
        launch_gemm<EPI_TANH>(gx, w1x, b1, trow, t0 + dt * 0.5f, y1, nullptr, nullptr, nullptr, nullptr, 0.f);
        launch_gemm<EPI_TANH>(y1, w2x, b2, nullptr, 0.f, y2, nullptr, nullptr, nullptr, nullptr, 0.f);
        launch_gemm<EPI_KMID>(y2, w3x, b3, nullptr, 0.f, gx, nullptr, hs, ks, nullptr, dt * 0.5f);
        // k3 = f(t0+dt/2, h + dt/2*k2)
        launch_gemm<EPI_TANH>(gx, w1x, b1, trow, t0 + dt * 0.5f, y1, nullptr, nullptr, nullptr, nullptr, 0.f);
        launch_gemm<EPI_TANH>(y1, w2x, b2, nullptr, 0.f, y2, nullptr, nullptr, nullptr, nullptr, 0.f);
        launch_gemm<EPI_KMID>(y2, w3x, b3, nullptr, 0.f, gx, nullptr, hs, ks, nullptr, dt);
        // k4 = f(t0+dt, h + dt*k3); h' = h + dt/6*(ksum + k4)
        launch_gemm<EPI_TANH>(gx, w1x, b1, trow, t0 + dt, y1, nullptr, nullptr, nullptr, nullptr, 0.f);
        launch_gemm<EPI_TANH>(y1, w2x, b2, nullptr, 0.f, y2, nullptr, nullptr, nullptr, nullptr, 0.f);
        launch_gemm<EPI_K4>(y2, w3x, b3, nullptr, 0.f, hs, hin, nullptr, ks, hdst, dt / 6.0f);
    }
}

// round 13
// speedup vs baseline: 1.0633x; 1.0178x over previous
#include <cuda_runtime.h>
#include <cuda_fp16.h>
#include <math.h>
#include <stddef.h>
#include <stdint.h>

// ---------------------------------------------------------------------------
// NeuralODE via fp16 mma.sync GEMM. CTA tile 128x128, 256 threads (8 warps,
// 64x32 warp tiles), BK=32, NBUF=4, single __syncthreads per stage, 2 CTAs
// per SM. PDL (griddepcontrol) overlaps each kernel's weight-tile prefetch
// with the predecessor's epilogue/tail. ksum fp16; K1/KMID read h as fp16.
// ---------------------------------------------------------------------------

#define MDIM 8192
#define NDIM 1024
#define KDIM 1024
#define STEPS_N 10

enum EpiMode { EPI_TANH = 0, EPI_K1 = 1, EPI_KMID = 2, EPI_K4 = 3 };

constexpr int BM = 128, BN = 128, BK = 32;
constexpr int NT = 256;
constexpr int NSTAGES = KDIM / BK;  // 32
constexpr int NBUF = 4;

// smem tile: 128 rows x 32 fp16, row stride 80 B (16*5, conflict-free ldsm)
constexpr int RSB = 80;
constexpr int TILE_B = 128 * RSB;          // 10240
constexpr int T_A = 0, T_B = TILE_B;
constexpr int STAGE_B = 2 * TILE_B;        // 20480
constexpr int SMEM_TOTAL = NBUF * STAGE_B; // 81920 (2 CTAs -> 160KB/SM)

// ---- global scratch ------------------------------------------------------
__device__ float g_f32[1ull * MDIM * NDIM];           // gh (fp32 state)
__device__ unsigned short g_bf[5ull * MDIM * NDIM];   // hs, gx, y1, y2, ksum
__device__ unsigned short g_wt[3ull * KDIM * NDIM];   // w1..w3 (fp16)

// ---- PTX helpers ---------------------------------------------------------

__device__ __forceinline__ uint32_t smem_to_u32(const void* p) {
    uint32_t a;
    asm("{ .reg .u64 t; cvta.to.shared.u64 t, %1; cvt.u32.u64 %0, t; }"
        : "=r"(a) : "l"(p));
    return a;
}

#define CP_ASYNC16(saddr, gptr)                                   \
    asm volatile("cp.async.cg.shared.global [%0], [%1], 16;" ::   \
                     "r"(saddr), "l"(gptr))
#define CP_COMMIT() asm volatile("cp.async.commit_group;" ::: "memory")
#define CP_WAIT2() asm volatile("cp.async.wait_group 2;" ::: "memory")
#define CP_WAIT1() asm volatile("cp.async.wait_group 1;" ::: "memory")
#define CP_WAIT0() asm volatile("cp.async.wait_group 0;" ::: "memory")

#define GRIDDEP_WAIT() asm volatile("griddepcontrol.wait;" ::: "memory")
#define GRIDDEP_LAUNCH() \
    asm volatile("griddepcontrol.launch_dependents;" ::: "memory")

#define LDSM_X4(r0, r1, r2, r3, addr)                                     \
    asm volatile("ldmatrix.sync.aligned.m8n8.x4.shared.b16 "              \
                 "{%0,%1,%2,%3}, [%4];"                                   \
                 : "=r"(r0), "=r"(r1), "=r"(r2), "=r"(r3) : "r"(addr))

#define MMA_F16(D, A, B)                                                   \
    asm volatile("mma.sync.aligned.m16n8k16.row.col.f32.f16.f16.f32 "      \
                 "{%0,%1,%2,%3}, {%4,%5,%6,%7}, {%8,%9}, {%0,%1,%2,%3};"   \
                 : "+f"((D)[0]), "+f"((D)[1]), "+f"((D)[2]), "+f"((D)[3])  \
                 : "r"((A)[0]), "r"((A)[1]), "r"((A)[2]), "r"((A)[3]),     \
                   "r"((B)[0]), "r"((B)[1]))

__device__ __forceinline__ float fast_tanh(float x) {
    float r;
    asm("tanh.approx.f32 %0, %1;" : "=f"(r) : "f"(x));
    return r;
}

__device__ __forceinline__ float4 ld4(const float* p) { return *(const float4*)p; }

__device__ __forceinline__ uint32_t pack_h2(float a, float b) {
    __half2 h = __floats2half2_rn(a, b);
    return *(uint32_t*)&h;
}

__device__ __forceinline__ float2 unpack_h2(uint32_t u) {
    __half2 h = *(__half2*)&u;
    return __half22float2(h);
}

// ---- weight convert+transpose: out[n][k] = fp16(W[k][n]) -----------------

__global__ void wsplit_kernel(const float* __restrict__ W,
                              unsigned short* __restrict__ hi) {
    __shared__ float t[32][33];
    const int tx = threadIdx.x, ty = threadIdx.y;
    const int n0 = blockIdx.x * 32, k0 = blockIdx.y * 32;
#pragma unroll
    for (int j = 0; j < 32; j += 8)
        t[ty + j][tx] = W[(size_t)(k0 + ty + j) * NDIM + n0 + tx];
    __syncthreads();
#pragma unroll
    for (int j = 0; j < 32; j += 8) {
        float v = t[tx][ty + j];
        __half h = __float2half_rn(v);
        hi[(size_t)(n0 + ty + j) * KDIM + k0 + tx] = *(unsigned short*)&h;
    }
}

// ---- activation convert (h0 prologue) ------------------------------------

__global__ void asplit_kernel(const float* __restrict__ X,
                              unsigned short* __restrict__ hi) {
    size_t i = ((size_t)blockIdx.x * blockDim.x + threadIdx.x) * 4;
    float4 v = ld4(X + i);
    *(uint2*)(hi + i) = make_uint2(pack_h2(v.x, v.y), pack_h2(v.z, v.w));
}

// ---- fused epilogue per (row, col-pair) ----------------------------------
// ksum fp16. K1/KMID read h via hb16 (fp16); K4 reads fp32 hbase.

template <int EPI>
__device__ __forceinline__ void epi_rc(int m, int c, float v0, float v1,
                                       unsigned short* oh,
                                       const float* hbase,
                                       const unsigned short* hb16,
                                       unsigned short* ksum,
                                       float* hout, float coef) {
    const size_t idx = (size_t)m * NDIM + c;
    if (EPI == EPI_TANH) {
        *(uint32_t*)(oh + idx) = pack_h2(fast_tanh(v0), fast_tanh(v1));
    } else if (EPI == EPI_K1) {
        *(uint32_t*)(ksum + idx) = pack_h2(v0, v1);
        float2 h = unpack_h2(*(const uint32_t*)(hb16 + idx));
        *(uint32_t*)(oh + idx) =
            pack_h2(fmaf(coef, v0, h.x), fmaf(coef, v1, h.y));
    } else if (EPI == EPI_KMID) {
        float2 s = unpack_h2(*(uint32_t*)(ksum + idx));
        s.x = fmaf(2.f, v0, s.x);
        s.y = fmaf(2.f, v1, s.y);
        *(uint32_t*)(ksum + idx) = pack_h2(s.x, s.y);
        float2 h = unpack_h2(*(const uint32_t*)(hb16 + idx));
        *(uint32_t*)(oh + idx) =
            pack_h2(fmaf(coef, v0, h.x), fmaf(coef, v1, h.y));
    } else {  // EPI_K4: oh = hs snapshot for next step (fp16), hout fp32
        float2 s = unpack_h2(*(uint32_t*)(ksum + idx));
        float2 h = *(const float2*)(hbase + idx);
        float g0 = fmaf(coef, s.x + v0, h.x);
        float g1 = fmaf(coef, s.y + v1, h.y);
        *(float2*)(hout + idx) = make_float2(g0, g1);
        *(uint32_t*)(oh + idx) = pack_h2(g0, g1);
    }
}

// ---- main GEMM -----------------------------------------------------------

template <int EPI>
__global__ void __launch_bounds__(NT, 2)
ngemm_kernel(const unsigned short* __restrict__ Ax,
             const unsigned short* __restrict__ Bx,
             const float* __restrict__ bias,
             const float* __restrict__ trow, float tval,
             unsigned short* __restrict__ oh,
             const float* __restrict__ hbase,
             const unsigned short* __restrict__ hb16,
             unsigned short* __restrict__ ksum,
             float* __restrict__ hout, float coef) {
    extern __shared__ char smc[];
    const uint32_t sb = smem_to_u32(smc);
    const int tid = threadIdx.x;
    const int lane = tid & 31;
    const int w = tid >> 5;
    const int wm = w & 1;        // 2 x 64 rows
    const int wn = w >> 1;       // 4 x 32 cols
    const int bm = blockIdx.y * BM;
    const int bn = blockIdx.x * BN;

    // cp.async chunk mapping: 512 x 16B chunks per tile, 2 per thread
    const int ch0 = tid, ch1 = tid + NT;
    const int r0 = ch0 >> 2, e0 = (ch0 & 3) * 8;
    const int r1 = ch1 >> 2, e1 = (ch1 & 3) * 8;
    const unsigned short* ga0 = Ax + (size_t)(bm + r0) * KDIM + e0;
    const unsigned short* ga1 = Ax + (size_t)(bm + r1) * KDIM + e1;
    const unsigned short* gb0 = Bx + (size_t)(bn + r0) * KDIM + e0;
    const unsigned short* gb1 = Bx + (size_t)(bn + r1) * KDIM + e1;
    const uint32_t s0 = (uint32_t)(r0 * RSB + (ch0 & 3) * 16);
    const uint32_t s1 = (uint32_t)(r1 * RSB + (ch1 & 3) * 16);

    const uint32_t a_off = (uint32_t)((lane & 15) * RSB + ((lane & 16) ? 16 : 0));
    const uint32_t b_off = (uint32_t)(((lane & 7) + ((lane & 16) ? 8 : 0)) * RSB +
                                      ((lane & 8) ? 16 : 0));

    float acc[4][4][4];
#pragma unroll
    for (int i = 0; i < 4; i++)
#pragma unroll
        for (int j = 0; j < 4; j++)
#pragma unroll
            for (int q = 0; q < 4; q++) acc[i][j][q] = 0.f;

    // ---- PDL prologue: prefetch B (weights -- written at prep time, safe
    // to read before the predecessor kernel finishes) for stages 0..2.
    CP_ASYNC16(sb + 0 * STAGE_B + T_B + s0, gb0);
    CP_ASYNC16(sb + 0 * STAGE_B + T_B + s1, gb1);
    CP_ASYNC16(sb + 1 * STAGE_B + T_B + s0, gb0 + BK);
    CP_ASYNC16(sb + 1 * STAGE_B + T_B + s1, gb1 + BK);
    CP_ASYNC16(sb + 2 * STAGE_B + T_B + s0, gb0 + 2 * BK);
    CP_ASYNC16(sb + 2 * STAGE_B + T_B + s1, gb1 + 2 * BK);

    // Wait for the predecessor kernel (producer of Ax / epilogue operands)
    // to fully complete with memory visibility.
    GRIDDEP_WAIT();

    // A-tile prologue loads; one commit per stage.
    // Group contents: g0 = {6x B prefetch, A0}, g1 = {A1}, g2 = {A2}.
    // Stage-s consumption needs A_s (group s) and B_s (group 0 for s<=2);
    // the existing wait ladder (<=2 pending at stage 0) implies group 0
    // complete, which covers ALL prefetched B.
    {
        CP_ASYNC16(sb + 0 * STAGE_B + T_A + s0, ga0);
        CP_ASYNC16(sb + 0 * STAGE_B + T_A + s1, ga1);
        CP_COMMIT();
        CP_ASYNC16(sb + 1 * STAGE_B + T_A + s0, ga0 + BK);
        CP_ASYNC16(sb + 1 * STAGE_B + T_A + s1, ga1 + BK);
        CP_COMMIT();
        CP_ASYNC16(sb + 2 * STAGE_B + T_A + s0, ga0 + 2 * BK);
        CP_ASYNC16(sb + 2 * STAGE_B + T_A + s1, ga1 + 2 * BK);
        CP_COMMIT();
    }

#define ISSUE_STAGE(st)                                                   \
    do {                                                                  \
        const int _kc = (st) * BK;                                        \
        const uint32_t _b = sb + ((st) % NBUF) * STAGE_B;                 \
        CP_ASYNC16(_b + T_A + s0, ga0 + _kc);                             \
        CP_ASYNC16(_b + T_A + s1, ga1 + _kc);                             \
        CP_ASYNC16(_b + T_B + s0, gb0 + _kc);                             \
        CP_ASYNC16(_b + T_B + s1, gb1 + _kc);                             \
        CP_COMMIT();                                                      \
    } while (0)

#pragma unroll 1
    for (int s = 0; s < NSTAGES; ++s) {
        if (s + 2 < NSTAGES) {
            CP_WAIT2();
        } else if (s + 1 < NSTAGES) {
            CP_WAIT1();
        } else {
            CP_WAIT0();
        }
        __syncthreads();
        if (s + 3 < NSTAGES) ISSUE_STAGE(s + 3);

        const uint32_t base = sb + (s % NBUF) * STAGE_B;
#pragma unroll
        for (int ks = 0; ks < 2; ++ks) {
            uint32_t a_[4][4], b_[4][2];
#pragma unroll
            for (int i = 0; i < 4; ++i) {
                const uint32_t ra =
                    base + (uint32_t)((wm * 64 + i * 16) * RSB + ks * 32) + a_off;
                LDSM_X4(a_[i][0], a_[i][1], a_[i][2], a_[i][3], ra + T_A);
            }
#pragma unroll
            for (int jj = 0; jj < 2; ++jj) {
                const uint32_t rb =
                    base + (uint32_t)((wn * 32 + jj * 16) * RSB + ks * 32) + b_off;
                uint32_t t0, t1, t2, t3;
                LDSM_X4(t0, t1, t2, t3, rb + T_B);
                b_[2 * jj][0] = t0; b_[2 * jj][1] = t1;
                b_[2 * jj + 1][0] = t2; b_[2 * jj + 1][1] = t3;
            }
#pragma unroll
            for (int i = 0; i < 4; ++i)
#pragma unroll
                for (int j = 0; j < 4; ++j) {
                    MMA_F16(acc[i][j], a_[i], b_[j]);
                }
        }
    }
#undef ISSUE_STAGE

    // Mainloop done: allow the dependent kernel to launch and start its
    // weight prefetch while we run the epilogue and drain the tail wave.
    GRIDDEP_LAUNCH();

    // ---------------- epilogue -------------------------------------------
#pragma unroll
    for (int j = 0; j < 4; ++j) {
        const int c = bn + wn * 32 + j * 8 + (lane & 3) * 2;
        float bb0 = bias[c], bb1 = bias[c + 1];
        if (EPI == EPI_TANH && trow != nullptr) {
            bb0 = fmaf(tval, trow[c], bb0);
            bb1 = fmaf(tval, trow[c + 1], bb1);
        }
#pragma unroll
        for (int i = 0; i < 4; ++i) {
            const int m0 = bm + wm * 64 + i * 16 + (lane >> 2);
            epi_rc<EPI>(m0, c, acc[i][j][0] + bb0, acc[i][j][1] + bb1,
                        oh, hbase, hb16, ksum, hout, coef);
            epi_rc<EPI>(m0 + 8, c, acc[i][j][2] + bb0, acc[i][j][3] + bb1,
                        oh, hbase, hb16, ksum, hout, coef);
        }
    }
}

// ---------------------------------------------------------------------------

template <int EPI>
static inline void launch_gemm(const unsigned short* Ax, const unsigned short* Bx,
                               const float* bias, const float* trow, float tval,
                               unsigned short* oh, const float* hbase,
                               const unsigned short* hb16,
                               unsigned short* ksum, float* hout, float coef) {
    cudaLaunchConfig_t cfg = {};
    cfg.gridDim = dim3(NDIM / BN, MDIM / BM);
    cfg.blockDim = dim3(NT);
    cfg.dynamicSmemBytes = SMEM_TOTAL;
    cfg.stream = 0;
    cudaLaunchAttribute attr[1];
    attr[0].id = cudaLaunchAttributeProgrammaticStreamSerialization;
    attr[0].val.programmaticStreamSerializationAllowed = 1;
    cfg.attrs = attr;
    cfg.numAttrs = 1;
    cudaLaunchKernelEx(&cfg, ngemm_kernel<EPI>, Ax, Bx, bias, trow, tval,
                       oh, hbase, hb16, ksum, hout, coef);
}

extern "C" void kernel_launch(void* const* d_in, const int* in_sizes, int n_in,
                              void* d_out, int out_size) {
    const float* h0 = (const float*)d_in[0];
    const float* W1 = (const float*)d_in[1];
    const float* b1 = (const float*)d_in[2];
    const float* W2 = (const float*)d_in[3];
    const float* b2 = (const float*)d_in[4];
    const float* W3 = (const float*)d_in[5];
    const float* b3 = (const float*)d_in[6];
    float* out = (float*)d_out;

    cudaFuncSetAttribute(ngemm_kernel<EPI_TANH>,
                         cudaFuncAttributeMaxDynamicSharedMemorySize, SMEM_TOTAL);
    cudaFuncSetAttribute(ngemm_kernel<EPI_K1>,
                         cudaFuncAttributeMaxDynamicSharedMemorySize, SMEM_TOTAL);
    cudaFuncSetAttribute(ngemm_kernel<EPI_KMID>,
                         cudaFuncAttributeMaxDynamicSharedMemorySize, SMEM_TOTAL);
    cudaFuncSetAttribute(ngemm_kernel<EPI_K4>,
                         cudaFuncAttributeMaxDynamicSharedMemorySize, SMEM_TOTAL);

    float* fbase = nullptr;
    cudaGetSymbolAddress((void**)&fbase, g_f32);
    unsigned short* abase = nullptr;
    cudaGetSymbolAddress((void**)&abase, g_bf);
    unsigned short* wbase = nullptr;
    cudaGetSymbolAddress((void**)&wbase, g_wt);

    const size_t SZ = (size_t)MDIM * NDIM;
    float* gh = fbase;                     // carried fp32 state

    unsigned short* hs = abase;            // fp16 snapshot of step-start h
    unsigned short* gx = abase + SZ;       // dynamics input fp16
    unsigned short* y1 = abase + 2 * SZ;
    unsigned short* y2 = abase + 3 * SZ;
    unsigned short* ks = abase + 4 * SZ;   // ksum fp16

    const size_t WSZ = (size_t)KDIM * NDIM;
    unsigned short* w1x = wbase;
    unsigned short* w2x = wbase + WSZ;
    unsigned short* w3x = wbase + 2 * WSZ;

    {
        dim3 g(NDIM / 32, KDIM / 32), b(32, 8);
        wsplit_kernel<<<g, b>>>(W1, w1x);
        wsplit_kernel<<<g, b>>>(W2, w2x);
        wsplit_kernel<<<g, b>>>(W3, w3x);
        asplit_kernel<<<(int)(SZ / 4 / 256), 256>>>(h0, hs);
    }

    const float dt = 0.1f;
    const float* trow = W1 + (size_t)KDIM * NDIM;  // W1 row 1024 (t row)

    for (int s = 0; s < STEPS_N; s++) {
        const float t0 = dt * (float)s;
        const float* hin = (s == 0) ? h0 : gh;
        float* hdst = (s == STEPS_N - 1) ? out : gh;

        // k1 = f(t0, h)
        launch_gemm<EPI_TANH>(hs, w1x, b1, trow, t0, y1, nullptr, nullptr, nullptr, nullptr, 0.f);
        launch_gemm<EPI_TANH>(y1, w2x, b2, nullptr, 0.f, y2, nullptr, nullptr, nullptr, nullptr, 0.f);
        launch_gemm<EPI_K1>(y2, w3x, b3, nullptr, 0.f, gx, nullptr, hs, ks, nullptr, dt * 0.5f);
        // k2 = f(t0+dt/2, h + dt/2*k1)
        launch_gemm<EPI_TANH>(gx, w1x, b1, trow, t0 + dt * 0.5f, y1, nullptr, nullptr, nullptr, nullptr, 0.f);
        launch_gemm<EPI_TANH>(y1, w2x, b2, nullptr, 0.f, y2, nullptr, nullptr, nullptr, nullptr, 0.f);
        launch_gemm<EPI_KMID>(y2, w3x, b3, nullptr, 0.f, gx, nullptr, hs, ks, nullptr, dt * 0.5f);
        // k3 = f(t0+dt/2, h + dt/2*k2)
        launch_gemm<EPI_TANH>(gx, w1x, b1, trow, t0 + dt * 0.5f, y1, nullptr, nullptr, nullptr, nullptr, 0.f);
        launch_gemm<EPI_TANH>(y1, w2x, b2, nullptr, 0.f, y2, nullptr, nullptr, nullptr, nullptr, 0.f);
        launch_gemm<EPI_KMID>(y2, w3x, b3, nullptr, 0.f, gx, nullptr, hs, ks, nullptr, dt);
        // k4 = f(t0+dt, h + dt*k3); h' = h + dt/6*(ksum + k4)
        launch_gemm<EPI_TANH>(gx, w1x, b1, trow, t0 + dt, y1, nullptr, nullptr, nullptr, nullptr, 0.f);
        launch_gemm<EPI_TANH>(y1, w2x, b2, nullptr, 0.f, y2, nullptr, nullptr, nullptr, nullptr, 0.f);
        launch_gemm<EPI_K4>(y2, w3x, b3, nullptr, 0.f, hs, hin, nullptr, ks, hdst, dt / 6.0f);
    }
}

// round 14
// speedup vs baseline: 1.1501x; 1.0816x over previous
#include <cuda_runtime.h>
#include <cuda_fp16.h>
#include <math.h>
#include <stddef.h>
#include <stdint.h>

// ---------------------------------------------------------------------------
// NeuralODE via fp16 mma.sync GEMM. CTA tile 128x128, 256 threads (8 warps,
// 64x32 warp tiles), BK=64 (16 stages), NBUF=3, single __syncthreads per
// stage, 2 CTAs per SM, PDL weight prefetch. ksum fp16; K1/KMID read h fp16.
// 120 GEMMs of [8192x1024]x[1024x1024]; epilogues fuse tanh / RK4 combines.
// ---------------------------------------------------------------------------

#define MDIM 8192
#define NDIM 1024
#define KDIM 1024
#define STEPS_N 10

enum EpiMode { EPI_TANH = 0, EPI_K1 = 1, EPI_KMID = 2, EPI_K4 = 3 };

constexpr int BM = 128, BN = 128, BK = 64;
constexpr int NT = 256;
constexpr int NSTAGES = KDIM / BK;  // 16
constexpr int NBUF = 3;

// smem tile: 128 rows x 64 fp16 (128B) padded to 144B row stride.
// 144 = 16*9, 9 coprime 8 -> conflict-free ldmatrix across 8-row groups.
constexpr int RSB = 144;
constexpr int TILE_B = 128 * RSB;          // 18432
constexpr int T_A = 0, T_B = TILE_B;
constexpr int STAGE_B = 2 * TILE_B;        // 36864
constexpr int SMEM_TOTAL = NBUF * STAGE_B; // 110592 (2 CTAs -> 221KB/SM)

// ---- global scratch ------------------------------------------------------
__device__ float g_f32[1ull * MDIM * NDIM];           // gh (fp32 state)
__device__ unsigned short g_bf[5ull * MDIM * NDIM];   // hs, gx, y1, y2, ksum
__device__ unsigned short g_wt[3ull * KDIM * NDIM];   // w1..w3 (fp16)

// ---- PTX helpers ---------------------------------------------------------

__device__ __forceinline__ uint32_t smem_to_u32(const void* p) {
    uint32_t a;
    asm("{ .reg .u64 t; cvta.to.shared.u64 t, %1; cvt.u32.u64 %0, t; }"
        : "=r"(a) : "l"(p));
    return a;
}

#define CP_ASYNC16(saddr, gptr)                                   \
    asm volatile("cp.async.cg.shared.global [%0], [%1], 16;" ::   \
                     "r"(saddr), "l"(gptr))
#define CP_COMMIT() asm volatile("cp.async.commit_group;" ::: "memory")
#define CP_WAIT1() asm volatile("cp.async.wait_group 1;" ::: "memory")
#define CP_WAIT0() asm volatile("cp.async.wait_group 0;" ::: "memory")

#define GRIDDEP_WAIT() asm volatile("griddepcontrol.wait;" ::: "memory")
#define GRIDDEP_LAUNCH() \
    asm volatile("griddepcontrol.launch_dependents;" ::: "memory")

#define LDSM_X4(r0, r1, r2, r3, addr)                                     \
    asm volatile("ldmatrix.sync.aligned.m8n8.x4.shared.b16 "              \
                 "{%0,%1,%2,%3}, [%4];"                                   \
                 : "=r"(r0), "=r"(r1), "=r"(r2), "=r"(r3) : "r"(addr))

#define MMA_F16(D, A, B)                                                   \
    asm volatile("mma.sync.aligned.m16n8k16.row.col.f32.f16.f16.f32 "      \
                 "{%0,%1,%2,%3}, {%4,%5,%6,%7}, {%8,%9}, {%0,%1,%2,%3};"   \
                 : "+f"((D)[0]), "+f"((D)[1]), "+f"((D)[2]), "+f"((D)[3])  \
                 : "r"((A)[0]), "r"((A)[1]), "r"((A)[2]), "r"((A)[3]),     \
                   "r"((B)[0]), "r"((B)[1]))

__device__ __forceinline__ float fast_tanh(float x) {
    float r;
    asm("tanh.approx.f32 %0, %1;" : "=f"(r) : "f"(x));
    return r;
}

__device__ __forceinline__ float4 ld4(const float* p) { return *(const float4*)p; }

__device__ __forceinline__ uint32_t pack_h2(float a, float b) {
    __half2 h = __floats2half2_rn(a, b);
    return *(uint32_t*)&h;
}

__device__ __forceinline__ float2 unpack_h2(uint32_t u) {
    __half2 h = *(__half2*)&u;
    return __half22float2(h);
}

// ---- weight convert+transpose: out[n][k] = fp16(W[k][n]) -----------------

__global__ void wsplit_kernel(const float* __restrict__ W,
                              unsigned short* __restrict__ hi) {
    __shared__ float t[32][33];
    const int tx = threadIdx.x, ty = threadIdx.y;
    const int n0 = blockIdx.x * 32, k0 = blockIdx.y * 32;
#pragma unroll
    for (int j = 0; j < 32; j += 8)
        t[ty + j][tx] = W[(size_t)(k0 + ty + j) * NDIM + n0 + tx];
    __syncthreads();
#pragma unroll
    for (int j = 0; j < 32; j += 8) {
        float v = t[tx][ty + j];
        __half h = __float2half_rn(v);
        hi[(size_t)(n0 + ty + j) * KDIM + k0 + tx] = *(unsigned short*)&h;
    }
}

// ---- activation convert (h0 prologue) ------------------------------------

__global__ void asplit_kernel(const float* __restrict__ X,
                              unsigned short* __restrict__ hi) {
    size_t i = ((size_t)blockIdx.x * blockDim.x + threadIdx.x) * 4;
    float4 v = ld4(X + i);
    *(uint2*)(hi + i) = make_uint2(pack_h2(v.x, v.y), pack_h2(v.z, v.w));
}

// ---- fused epilogue per (row, col-pair) ----------------------------------
// ksum fp16. K1/KMID read h via hb16 (fp16); K4 reads fp32 hbase.

template <int EPI>
__device__ __forceinline__ void epi_rc(int m, int c, float v0, float v1,
                                       unsigned short* oh,
                                       const float* hbase,
                                       const unsigned short* hb16,
                                       unsigned short* ksum,
                                       float* hout, float coef) {
    const size_t idx = (size_t)m * NDIM + c;
    if (EPI == EPI_TANH) {
        *(uint32_t*)(oh + idx) = pack_h2(fast_tanh(v0), fast_tanh(v1));
    } else if (EPI == EPI_K1) {
        *(uint32_t*)(ksum + idx) = pack_h2(v0, v1);
        float2 h = unpack_h2(*(const uint32_t*)(hb16 + idx));
        *(uint32_t*)(oh + idx) =
            pack_h2(fmaf(coef, v0, h.x), fmaf(coef, v1, h.y));
    } else if (EPI == EPI_KMID) {
        float2 s = unpack_h2(*(uint32_t*)(ksum + idx));
        s.x = fmaf(2.f, v0, s.x);
        s.y = fmaf(2.f, v1, s.y);
        *(uint32_t*)(ksum + idx) = pack_h2(s.x, s.y);
        float2 h = unpack_h2(*(const uint32_t*)(hb16 + idx));
        *(uint32_t*)(oh + idx) =
            pack_h2(fmaf(coef, v0, h.x), fmaf(coef, v1, h.y));
    } else {  // EPI_K4: oh = hs snapshot for next step (fp16), hout fp32
        float2 s = unpack_h2(*(uint32_t*)(ksum + idx));
        float2 h = *(const float2*)(hbase + idx);
        float g0 = fmaf(coef, s.x + v0, h.x);
        float g1 = fmaf(coef, s.y + v1, h.y);
        *(float2*)(hout + idx) = make_float2(g0, g1);
        *(uint32_t*)(oh + idx) = pack_h2(g0, g1);
    }
}

// ---- main GEMM -----------------------------------------------------------

template <int EPI>
__global__ void __launch_bounds__(NT, 2)
ngemm_kernel(const unsigned short* __restrict__ Ax,
             const unsigned short* __restrict__ Bx,
             const float* __restrict__ bias,
             const float* __restrict__ trow, float tval,
             unsigned short* __restrict__ oh,
             const float* __restrict__ hbase,
             const unsigned short* __restrict__ hb16,
             unsigned short* __restrict__ ksum,
             float* __restrict__ hout, float coef) {
    extern __shared__ char smc[];
    const uint32_t sb = smem_to_u32(smc);
    const int tid = threadIdx.x;
    const int lane = tid & 31;
    const int w = tid >> 5;
    const int wm = w & 1;        // 2 x 64 rows
    const int wn = w >> 1;       // 4 x 32 cols
    const int bm = blockIdx.y * BM;
    const int bn = blockIdx.x * BN;

    // cp.async: 1024 x 16B chunks per tile (128 rows x 8), 4 per thread.
    // thread -> base row tid>>3, 16B column tid&7; k adds 32 rows.
    const int cr = tid >> 3;              // 0..31
    const int cc = (tid & 7) * 8;         // fp16 col offset
    const unsigned short* gaP[4];
    const unsigned short* gbP[4];
    uint32_t scP[4];
#pragma unroll
    for (int k = 0; k < 4; ++k) {
        const int row = k * 32 + cr;
        gaP[k] = Ax + (size_t)(bm + row) * KDIM + cc;
        gbP[k] = Bx + (size_t)(bn + row) * KDIM + cc;
        scP[k] = (uint32_t)(row * RSB + (tid & 7) * 16);
    }

    const uint32_t a_off = (uint32_t)((lane & 15) * RSB + ((lane & 16) ? 16 : 0));
    const uint32_t b_off = (uint32_t)(((lane & 7) + ((lane & 16) ? 8 : 0)) * RSB +
                                      ((lane & 8) ? 16 : 0));

    float acc[4][4][4];
#pragma unroll
    for (int i = 0; i < 4; i++)
#pragma unroll
        for (int j = 0; j < 4; j++)
#pragma unroll
            for (int q = 0; q < 4; q++) acc[i][j][q] = 0.f;

    // ---- PDL prologue: prefetch B (weights, written at prep time) for
    // stages 0 and 1 before waiting on the predecessor kernel.
#pragma unroll
    for (int k = 0; k < 4; ++k) {
        CP_ASYNC16(sb + 0 * STAGE_B + T_B + scP[k], gbP[k]);
        CP_ASYNC16(sb + 1 * STAGE_B + T_B + scP[k], gbP[k] + BK);
    }

    // Wait for the predecessor (producer of Ax / epilogue operands).
    GRIDDEP_WAIT();

    // A prologue loads. Groups: g0 = {8x B prefetch, A0}, g1 = {A1}.
    // Stage-0 wait (<=1 pending) implies g0 complete -> all B covered.
#pragma unroll
    for (int k = 0; k < 4; ++k)
        CP_ASYNC16(sb + 0 * STAGE_B + T_A + scP[k], gaP[k]);
    CP_COMMIT();
#pragma unroll
    for (int k = 0; k < 4; ++k)
        CP_ASYNC16(sb + 1 * STAGE_B + T_A + scP[k], gaP[k] + BK);
    CP_COMMIT();

#define ISSUE_STAGE(st)                                                   \
    do {                                                                  \
        const int _kc = (st) * BK;                                        \
        const uint32_t _b = sb + ((st) % NBUF) * STAGE_B;                 \
        _Pragma("unroll")                                                 \
        for (int _k = 0; _k < 4; ++_k) {                                  \
            CP_ASYNC16(_b + T_A + scP[_k], gaP[_k] + _kc);                \
            CP_ASYNC16(_b + T_B + scP[_k], gbP[_k] + _kc);                \
        }                                                                 \
        CP_COMMIT();                                                      \
    } while (0)

#pragma unroll 1
    for (int s = 0; s < NSTAGES; ++s) {
        // Ensure group s complete; pending is a subset of {s, s+1}
        // (ISSUE(s+2) happens after the barrier below).
        if (s + 1 < NSTAGES) {
            CP_WAIT1();
        } else {
            CP_WAIT0();
        }
        // Single barrier: stage-s data visible AND buffer (s-1)%NBUF fully
        // consumed (read in stage s-1, before this barrier), so ISSUE(s+2)
        // may overwrite it.
        __syncthreads();
        if (s + 2 < NSTAGES) ISSUE_STAGE(s + 2);

        const uint32_t base = sb + (s % NBUF) * STAGE_B;
#pragma unroll
        for (int ks = 0; ks < 4; ++ks) {
            uint32_t a_[4][4], b_[4][2];
#pragma unroll
            for (int i = 0; i < 4; ++i) {
                const uint32_t ra =
                    base + (uint32_t)((wm * 64 + i * 16) * RSB + ks * 32) + a_off;
                LDSM_X4(a_[i][0], a_[i][1], a_[i][2], a_[i][3], ra + T_A);
            }
#pragma unroll
            for (int jj = 0; jj < 2; ++jj) {
                const uint32_t rb =
                    base + (uint32_t)((wn * 32 + jj * 16) * RSB + ks * 32) + b_off;
                uint32_t t0, t1, t2, t3;
                LDSM_X4(t0, t1, t2, t3, rb + T_B);
                b_[2 * jj][0] = t0; b_[2 * jj][1] = t1;
                b_[2 * jj + 1][0] = t2; b_[2 * jj + 1][1] = t3;
            }
#pragma unroll
            for (int i = 0; i < 4; ++i)
#pragma unroll
                for (int j = 0; j < 4; ++j) {
                    MMA_F16(acc[i][j], a_[i], b_[j]);
                }
        }
    }
#undef ISSUE_STAGE

    // Mainloop done: let the dependent kernel launch + prefetch weights
    // while we run the epilogue and drain the tail wave.
    GRIDDEP_LAUNCH();

    // ---------------- epilogue -------------------------------------------
#pragma unroll
    for (int j = 0; j < 4; ++j) {
        const int c = bn + wn * 32 + j * 8 + (lane & 3) * 2;
        float bb0 = bias[c], bb1 = bias[c + 1];
        if (EPI == EPI_TANH && trow != nullptr) {
            bb0 = fmaf(tval, trow[c], bb0);
            bb1 = fmaf(tval, trow[c + 1], bb1);
        }
#pragma unroll
        for (int i = 0; i < 4; ++i) {
            const int m0 = bm + wm * 64 + i * 16 + (lane >> 2);
            epi_rc<EPI>(m0, c, acc[i][j][0] + bb0, acc[i][j][1] + bb1,
                        oh, hbase, hb16, ksum, hout, coef);
            epi_rc<EPI>(m0 + 8, c, acc[i][j][2] + bb0, acc[i][j][3] + bb1,
                        oh, hbase, hb16, ksum, hout, coef);
        }
    }
}

// ---------------------------------------------------------------------------

template <int EPI>
static inline void launch_gemm(const unsigned short* Ax, const unsigned short* Bx,
                               const float* bias, const float* trow, float tval,
                               unsigned short* oh, const float* hbase,
                               const unsigned short* hb16,
                               unsigned short* ksum, float* hout, float coef) {
    cudaLaunchConfig_t cfg = {};
    cfg.gridDim = dim3(NDIM / BN, MDIM / BM);
    cfg.blockDim = dim3(NT);
    cfg.dynamicSmemBytes = SMEM_TOTAL;
    cfg.stream = 0;
    cudaLaunchAttribute attr[1];
    attr[0].id = cudaLaunchAttributeProgrammaticStreamSerialization;
    attr[0].val.programmaticStreamSerializationAllowed = 1;
    cfg.attrs = attr;
    cfg.numAttrs = 1;
    cudaLaunchKernelEx(&cfg, ngemm_kernel<EPI>, Ax, Bx, bias, trow, tval,
                       oh, hbase, hb16, ksum, hout, coef);
}

extern "C" void kernel_launch(void* const* d_in, const int* in_sizes, int n_in,
                              void* d_out, int out_size) {
    const float* h0 = (const float*)d_in[0];
    const float* W1 = (const float*)d_in[1];
    const float* b1 = (const float*)d_in[2];
    const float* W2 = (const float*)d_in[3];
    const float* b2 = (const float*)d_in[4];
    const float* W3 = (const float*)d_in[5];
    const float* b3 = (const float*)d_in[6];
    float* out = (float*)d_out;

    cudaFuncSetAttribute(ngemm_kernel<EPI_TANH>,
                         cudaFuncAttributeMaxDynamicSharedMemorySize, SMEM_TOTAL);
    cudaFuncSetAttribute(ngemm_kernel<EPI_K1>,
                         cudaFuncAttributeMaxDynamicSharedMemorySize, SMEM_TOTAL);
    cudaFuncSetAttribute(ngemm_kernel<EPI_KMID>,
                         cudaFuncAttributeMaxDynamicSharedMemorySize, SMEM_TOTAL);
    cudaFuncSetAttribute(ngemm_kernel<EPI_K4>,
                         cudaFuncAttributeMaxDynamicSharedMemorySize, SMEM_TOTAL);

    float* fbase = nullptr;
    cudaGetSymbolAddress((void**)&fbase, g_f32);
    unsigned short* abase = nullptr;
    cudaGetSymbolAddress((void**)&abase, g_bf);
    unsigned short* wbase = nullptr;
    cudaGetSymbolAddress((void**)&wbase, g_wt);

    const size_t SZ = (size_t)MDIM * NDIM;
    float* gh = fbase;                     // carried fp32 state

    unsigned short* hs = abase;            // fp16 snapshot of step-start h
    unsigned short* gx = abase + SZ;       // dynamics input fp16
    unsigned short* y1 = abase + 2 * SZ;
    unsigned short* y2 = abase + 3 * SZ;
    unsigned short* ks = abase + 4 * SZ;   // ksum fp16

    const size_t WSZ = (size_t)KDIM * NDIM;
    unsigned short* w1x = wbase;
    unsigned short* w2x = wbase + WSZ;
    unsigned short* w3x = wbase + 2 * WSZ;

    {
        dim3 g(NDIM / 32, KDIM / 32), b(32, 8);
        wsplit_kernel<<<g, b>>>(W1, w1x);
        wsplit_kernel<<<g, b>>>(W2, w2x);
        wsplit_kernel<<<g, b>>>(W3, w3x);
        asplit_kernel<<<(int)(SZ / 4 / 256), 256>>>(h0, hs);
    }

    const float dt = 0.1f;
    const float* trow = W1 + (size_t)KDIM * NDIM;  // W1 row 1024 (t row)

    for (int s = 0; s < STEPS_N; s++) {
        const float t0 = dt * (float)s;
        const float* hin = (s == 0) ? h0 : gh;
        float* hdst = (s == STEPS_N - 1) ? out : gh;

        // k1 = f(t0, h)
        launch_gemm<EPI_TANH>(hs, w1x, b1, trow, t0, y1, nullptr, nullptr, nullptr, nullptr, 0.f);
        launch_gemm<EPI_TANH>(y1, w2x, b2, nullptr, 0.f, y2, nullptr, nullptr, nullptr, nullptr, 0.f);
        launch_gemm<EPI_K1>(y2, w3x, b3, nullptr, 0.f, gx, nullptr, hs, ks, nullptr, dt * 0.5f);
        // k2 = f(t0+dt/2, h + dt/2*k1)
        launch_gemm<EPI_TANH>(gx, w1x, b1, trow, t0 + dt * 0.5f, y1, nullptr, nullptr, nullptr, nullptr, 0.f);
        launch_gemm<EPI_TANH>(y1, w2x, b2, nullptr, 0.f, y2, nullptr, nullptr, nullptr, nullptr, 0.f);
        launch_gemm<EPI_KMID>(y2, w3x, b3, nullptr, 0.f, gx, nullptr, hs, ks, nullptr, dt * 0.5f);
        // k3 = f(t0+dt/2, h + dt/2*k2)
        launch_gemm<EPI_TANH>(gx, w1x, b1, trow, t0 + dt * 0.5f, y1, nullptr, nullptr, nullptr, nullptr, 0.f);
        launch_gemm<EPI_TANH>(y1, w2x, b2, nullptr, 0.f, y2, nullptr, nullptr, nullptr, nullptr, 0.f);
        launch_gemm<EPI_KMID>(y2, w3x, b3, nullptr, 0.f, gx, nullptr, hs, ks, nullptr, dt);
        // k4 = f(t0+dt, h + dt*k3); h' = h + dt/6*(ksum + k4)
        launch_gemm<EPI_TANH>(gx, w1x, b1, trow, t0 + dt, y1, nullptr, nullptr, nullptr, nullptr, 0.f);
        launch_gemm<EPI_TANH>(y1, w2x, b2, nullptr, 0.f, y2, nullptr, nullptr, nullptr, nullptr, 0.f);
        launch_gemm<EPI_K4>(y2, w3x, b3, nullptr, 0.f, hs, hin, nullptr, ks, hdst, dt / 6.0f);
    }
}

// round 15
// speedup vs baseline: 1.3603x; 1.1828x over previous
#include <cuda_runtime.h>
#include <cuda_fp16.h>
#include <math.h>
#include <stddef.h>
#include <stdint.h>

// ---------------------------------------------------------------------------
// NeuralODE via fp16 mma.sync GEMM. CTA tile 128x128, 8 warps (64x32 tiles),
// BK=64 (16 stages), NBUF=3, 2 CTAs/SM, PDL + per-rowblock cross-kernel
// flags: consumer CTAs wait only for their 128-row block of the producer,
// overlapping successive GEMMs' waves (recovers wave-quantization loss).
// ---------------------------------------------------------------------------

#define MDIM 8192
#define NDIM 1024
#define KDIM 1024
#define STEPS_N 10

enum EpiMode { EPI_TANH = 0, EPI_K1 = 1, EPI_KMID = 2, EPI_K4 = 3 };

constexpr int BM = 128, BN = 128, BK = 64;
constexpr int NT = 256;
constexpr int NSTAGES = KDIM / BK;  // 16
constexpr int NBUF = 3;
constexpr int NRB = MDIM / BM;      // 64 rowblocks
constexpr int NPROD = NDIM / BN;    // 8 producer tiles per rowblock

// smem tile: 128 rows x 64 fp16 (128B) padded to 144B row stride.
constexpr int RSB = 144;
constexpr int TILE_B = 128 * RSB;          // 18432
constexpr int T_A = 0, T_B = TILE_B;
constexpr int STAGE_B = 2 * TILE_B;        // 36864
constexpr int SMEM_TOTAL = NBUF * STAGE_B; // 110592 (2 CTAs -> 221KB/SM)

// ---- global scratch ------------------------------------------------------
__device__ float g_f32[1ull * MDIM * NDIM];           // gh (fp32 state)
__device__ unsigned short g_bf[5ull * MDIM * NDIM];   // hs, gx, y1, y2, ksum
__device__ unsigned short g_wt[3ull * KDIM * NDIM];   // w1..w3 (fp16)
__device__ int g_flags[120 * NRB];                    // rowblock readiness

// ---- PTX helpers ---------------------------------------------------------

__device__ __forceinline__ uint32_t smem_to_u32(const void* p) {
    uint32_t a;
    asm("{ .reg .u64 t; cvta.to.shared.u64 t, %1; cvt.u32.u64 %0, t; }"
        : "=r"(a) : "l"(p));
    return a;
}

#define CP_ASYNC16(saddr, gptr)                                   \
    asm volatile("cp.async.cg.shared.global [%0], [%1], 16;" ::   \
                     "r"(saddr), "l"(gptr))
#define CP_COMMIT() asm volatile("cp.async.commit_group;" ::: "memory")
#define CP_WAIT1() asm volatile("cp.async.wait_group 1;" ::: "memory")
#define CP_WAIT0() asm volatile("cp.async.wait_group 0;" ::: "memory")

#define GRIDDEP_WAIT() asm volatile("griddepcontrol.wait;" ::: "memory")
#define GRIDDEP_LAUNCH() \
    asm volatile("griddepcontrol.launch_dependents;" ::: "memory")

#define LDSM_X4(r0, r1, r2, r3, addr)                                     \
    asm volatile("ldmatrix.sync.aligned.m8n8.x4.shared.b16 "              \
                 "{%0,%1,%2,%3}, [%4];"                                   \
                 : "=r"(r0), "=r"(r1), "=r"(r2), "=r"(r3) : "r"(addr))

#define MMA_F16(D, A, B)                                                   \
    asm volatile("mma.sync.aligned.m16n8k16.row.col.f32.f16.f16.f32 "      \
                 "{%0,%1,%2,%3}, {%4,%5,%6,%7}, {%8,%9}, {%0,%1,%2,%3};"   \
                 : "+f"((D)[0]), "+f"((D)[1]), "+f"((D)[2]), "+f"((D)[3])  \
                 : "r"((A)[0]), "r"((A)[1]), "r"((A)[2]), "r"((A)[3]),     \
                   "r"((B)[0]), "r"((B)[1]))

__device__ __forceinline__ float fast_tanh(float x) {
    float r;
    asm("tanh.approx.f32 %0, %1;" : "=f"(r) : "f"(x));
    return r;
}

__device__ __forceinline__ float4 ld4(const float* p) { return *(const float4*)p; }

__device__ __forceinline__ uint32_t pack_h2(float a, float b) {
    __half2 h = __floats2half2_rn(a, b);
    return *(uint32_t*)&h;
}

__device__ __forceinline__ float2 unpack_h2(uint32_t u) {
    __half2 h = *(__half2*)&u;
    return __half22float2(h);
}

// ---- weight convert+transpose: out[n][k] = fp16(W[k][n]) -----------------

__global__ void wsplit_kernel(const float* __restrict__ W,
                              unsigned short* __restrict__ hi) {
    __shared__ float t[32][33];
    const int tx = threadIdx.x, ty = threadIdx.y;
    const int n0 = blockIdx.x * 32, k0 = blockIdx.y * 32;
#pragma unroll
    for (int j = 0; j < 32; j += 8)
        t[ty + j][tx] = W[(size_t)(k0 + ty + j) * NDIM + n0 + tx];
    __syncthreads();
#pragma unroll
    for (int j = 0; j < 32; j += 8) {
        float v = t[tx][ty + j];
        __half h = __float2half_rn(v);
        hi[(size_t)(n0 + ty + j) * KDIM + k0 + tx] = *(unsigned short*)&h;
    }
}

// ---- activation convert (h0 prologue) ------------------------------------

__global__ void asplit_kernel(const float* __restrict__ X,
                              unsigned short* __restrict__ hi) {
    size_t i = ((size_t)blockIdx.x * blockDim.x + threadIdx.x) * 4;
    float4 v = ld4(X + i);
    *(uint2*)(hi + i) = make_uint2(pack_h2(v.x, v.y), pack_h2(v.z, v.w));
}

// ---- fused epilogue per (row, col-pair) ----------------------------------

template <int EPI>
__device__ __forceinline__ void epi_rc(int m, int c, float v0, float v1,
                                       unsigned short* oh,
                                       const float* hbase,
                                       const unsigned short* hb16,
                                       unsigned short* ksum,
                                       float* hout, float coef) {
    const size_t idx = (size_t)m * NDIM + c;
    if (EPI == EPI_TANH) {
        *(uint32_t*)(oh + idx) = pack_h2(fast_tanh(v0), fast_tanh(v1));
    } else if (EPI == EPI_K1) {
        *(uint32_t*)(ksum + idx) = pack_h2(v0, v1);
        float2 h = unpack_h2(*(const uint32_t*)(hb16 + idx));
        *(uint32_t*)(oh + idx) =
            pack_h2(fmaf(coef, v0, h.x), fmaf(coef, v1, h.y));
    } else if (EPI == EPI_KMID) {
        float2 s = unpack_h2(*(uint32_t*)(ksum + idx));
        s.x = fmaf(2.f, v0, s.x);
        s.y = fmaf(2.f, v1, s.y);
        *(uint32_t*)(ksum + idx) = pack_h2(s.x, s.y);
        float2 h = unpack_h2(*(const uint32_t*)(hb16 + idx));
        *(uint32_t*)(oh + idx) =
            pack_h2(fmaf(coef, v0, h.x), fmaf(coef, v1, h.y));
    } else {  // EPI_K4
        float2 s = unpack_h2(*(uint32_t*)(ksum + idx));
        float2 h = *(const float2*)(hbase + idx);
        float g0 = fmaf(coef, s.x + v0, h.x);
        float g1 = fmaf(coef, s.y + v1, h.y);
        *(float2*)(hout + idx) = make_float2(g0, g1);
        *(uint32_t*)(oh + idx) = pack_h2(g0, g1);
    }
}

// ---- main GEMM -----------------------------------------------------------

template <int EPI>
__global__ void __launch_bounds__(NT, 2)
ngemm_kernel(const unsigned short* __restrict__ Ax,
             const unsigned short* __restrict__ Bx,
             const float* __restrict__ bias,
             const float* __restrict__ trow, float tval,
             unsigned short* __restrict__ oh,
             const float* __restrict__ hbase,
             const unsigned short* __restrict__ hb16,
             unsigned short* __restrict__ ksum,
             float* __restrict__ hout, float coef,
             const int* flag_in, int* flag_out) {
    extern __shared__ char smc[];
    const uint32_t sb = smem_to_u32(smc);
    const int tid = threadIdx.x;
    const int lane = tid & 31;
    const int w = tid >> 5;
    const int wm = w & 1;
    const int wn = w >> 1;
    const int bm = blockIdx.y * BM;
    const int bn = blockIdx.x * BN;

    // cp.async: 1024 x 16B chunks per tile, 4 per thread.
    const int cr = tid >> 3;
    const int cc = (tid & 7) * 8;
    const unsigned short* gaP[4];
    const unsigned short* gbP[4];
    uint32_t scP[4];
#pragma unroll
    for (int k = 0; k < 4; ++k) {
        const int row = k * 32 + cr;
        gaP[k] = Ax + (size_t)(bm + row) * KDIM + cc;
        gbP[k] = Bx + (size_t)(bn + row) * KDIM + cc;
        scP[k] = (uint32_t)(row * RSB + (tid & 7) * 16);
    }

    const uint32_t a_off = (uint32_t)((lane & 15) * RSB + ((lane & 16) ? 16 : 0));
    const uint32_t b_off = (uint32_t)(((lane & 7) + ((lane & 16) ? 8 : 0)) * RSB +
                                      ((lane & 8) ? 16 : 0));

    float acc[4][4][4];
#pragma unroll
    for (int i = 0; i < 4; i++)
#pragma unroll
        for (int j = 0; j < 4; j++)
#pragma unroll
            for (int q = 0; q < 4; q++) acc[i][j][q] = 0.f;

    // ---- B (weights) prefetch for stages 0,1: no data dependency.
#pragma unroll
    for (int k = 0; k < 4; ++k) {
        CP_ASYNC16(sb + 0 * STAGE_B + T_B + scP[k], gbP[k]);
        CP_ASYNC16(sb + 1 * STAGE_B + T_B + scP[k], gbP[k] + BK);
    }

    // Let the successor kernel be scheduled ASAP; its CTAs self-protect
    // via the per-rowblock flags.
    GRIDDEP_LAUNCH();

    if (flag_in != nullptr) {
        // Wait only for OUR 128-row block of the producer (8 tiles).
        if (tid == 0) {
            volatile int* fi = (volatile int*)(flag_in + blockIdx.y);
            while (*fi < NPROD) __nanosleep(64);
            __threadfence();  // acquire: producer stores now visible
            int old = atomicAdd((int*)(flag_in + blockIdx.y), 1);
            if (old == 2 * NPROD - 1)  // 16th arrival: reset for next replay
                atomicExch((int*)(flag_in + blockIdx.y), 0);
        }
        __syncthreads();
    } else {
        // First GEMM in the chain: depends on the (non-PDL) prep kernels.
        GRIDDEP_WAIT();
    }

    // A prologue loads. Groups: g0 = {8x B prefetch, A0}, g1 = {A1}.
#pragma unroll
    for (int k = 0; k < 4; ++k)
        CP_ASYNC16(sb + 0 * STAGE_B + T_A + scP[k], gaP[k]);
    CP_COMMIT();
#pragma unroll
    for (int k = 0; k < 4; ++k)
        CP_ASYNC16(sb + 1 * STAGE_B + T_A + scP[k], gaP[k] + BK);
    CP_COMMIT();

#define ISSUE_STAGE(st)                                                   \
    do {                                                                  \
        const int _kc = (st) * BK;                                        \
        const uint32_t _b = sb + ((st) % NBUF) * STAGE_B;                 \
        _Pragma("unroll")                                                 \
        for (int _k = 0; _k < 4; ++_k) {                                  \
            CP_ASYNC16(_b + T_A + scP[_k], gaP[_k] + _kc);                \
            CP_ASYNC16(_b + T_B + scP[_k], gbP[_k] + _kc);                \
        }                                                                 \
        CP_COMMIT();                                                      \
    } while (0)

#pragma unroll 1
    for (int s = 0; s < NSTAGES; ++s) {
        if (s + 1 < NSTAGES) {
            CP_WAIT1();
        } else {
            CP_WAIT0();
        }
        __syncthreads();
        if (s + 2 < NSTAGES) ISSUE_STAGE(s + 2);

        const uint32_t base = sb + (s % NBUF) * STAGE_B;
#pragma unroll
        for (int ks = 0; ks < 4; ++ks) {
            uint32_t a_[4][4], b_[4][2];
#pragma unroll
            for (int i = 0; i < 4; ++i) {
                const uint32_t ra =
                    base + (uint32_t)((wm * 64 + i * 16) * RSB + ks * 32) + a_off;
                LDSM_X4(a_[i][0], a_[i][1], a_[i][2], a_[i][3], ra + T_A);
            }
#pragma unroll
            for (int jj = 0; jj < 2; ++jj) {
                const uint32_t rb =
                    base + (uint32_t)((wn * 32 + jj * 16) * RSB + ks * 32) + b_off;
                uint32_t t0, t1, t2, t3;
                LDSM_X4(t0, t1, t2, t3, rb + T_B);
                b_[2 * jj][0] = t0; b_[2 * jj][1] = t1;
                b_[2 * jj + 1][0] = t2; b_[2 * jj + 1][1] = t3;
            }
#pragma unroll
            for (int i = 0; i < 4; ++i)
#pragma unroll
                for (int j = 0; j < 4; ++j) {
                    MMA_F16(acc[i][j], a_[i], b_[j]);
                }
        }
    }
#undef ISSUE_STAGE

    // ---------------- epilogue -------------------------------------------
#pragma unroll
    for (int j = 0; j < 4; ++j) {
        const int c = bn + wn * 32 + j * 8 + (lane & 3) * 2;
        float bb0 = bias[c], bb1 = bias[c + 1];
        if (EPI == EPI_TANH && trow != nullptr) {
            bb0 = fmaf(tval, trow[c], bb0);
            bb1 = fmaf(tval, trow[c + 1], bb1);
        }
#pragma unroll
        for (int i = 0; i < 4; ++i) {
            const int m0 = bm + wm * 64 + i * 16 + (lane >> 2);
            epi_rc<EPI>(m0, c, acc[i][j][0] + bb0, acc[i][j][1] + bb1,
                        oh, hbase, hb16, ksum, hout, coef);
            epi_rc<EPI>(m0 + 8, c, acc[i][j][2] + bb0, acc[i][j][3] + bb1,
                        oh, hbase, hb16, ksum, hout, coef);
        }
    }

    // Signal: this CTA's tile of rowblock blockIdx.y is complete.
    if (flag_out != nullptr) {
        __syncthreads();  // all threads' epilogue stores issued
        if (tid == 0) {
            __threadfence();  // release: stores visible GPU-wide
            atomicAdd(flag_out + blockIdx.y, 1);
        }
    }
}

// ---------------------------------------------------------------------------

template <int EPI>
static inline void launch_gemm(const unsigned short* Ax, const unsigned short* Bx,
                               const float* bias, const float* trow, float tval,
                               unsigned short* oh, const float* hbase,
                               const unsigned short* hb16,
                               unsigned short* ksum, float* hout, float coef,
                               const int* flag_in, int* flag_out) {
    cudaLaunchConfig_t cfg = {};
    cfg.gridDim = dim3(NDIM / BN, MDIM / BM);
    cfg.blockDim = dim3(NT);
    cfg.dynamicSmemBytes = SMEM_TOTAL;
    cfg.stream = 0;
    cudaLaunchAttribute attr[1];
    attr[0].id = cudaLaunchAttributeProgrammaticStreamSerialization;
    attr[0].val.programmaticStreamSerializationAllowed = 1;
    cfg.attrs = attr;
    cfg.numAttrs = 1;
    cudaLaunchKernelEx(&cfg, ngemm_kernel<EPI>, Ax, Bx, bias, trow, tval,
                       oh, hbase, hb16, ksum, hout, coef, flag_in, flag_out);
}

extern "C" void kernel_launch(void* const* d_in, const int* in_sizes, int n_in,
                              void* d_out, int out_size) {
    const float* h0 = (const float*)d_in[0];
    const float* W1 = (const float*)d_in[1];
    const float* b1 = (const float*)d_in[2];
    const float* W2 = (const float*)d_in[3];
    const float* b2 = (const float*)d_in[4];
    const float* W3 = (const float*)d_in[5];
    const float* b3 = (const float*)d_in[6];
    float* out = (float*)d_out;

    cudaFuncSetAttribute(ngemm_kernel<EPI_TANH>,
                         cudaFuncAttributeMaxDynamicSharedMemorySize, SMEM_TOTAL);
    cudaFuncSetAttribute(ngemm_kernel<EPI_K1>,
                         cudaFuncAttributeMaxDynamicSharedMemorySize, SMEM_TOTAL);
    cudaFuncSetAttribute(ngemm_kernel<EPI_KMID>,
                         cudaFuncAttributeMaxDynamicSharedMemorySize, SMEM_TOTAL);
    cudaFuncSetAttribute(ngemm_kernel<EPI_K4>,
                         cudaFuncAttributeMaxDynamicSharedMemorySize, SMEM_TOTAL);

    float* fbase = nullptr;
    cudaGetSymbolAddress((void**)&fbase, g_f32);
    unsigned short* abase = nullptr;
    cudaGetSymbolAddress((void**)&abase, g_bf);
    unsigned short* wbase = nullptr;
    cudaGetSymbolAddress((void**)&wbase, g_wt);
    int* flbase = nullptr;
    cudaGetSymbolAddress((void**)&flbase, g_flags);

    const size_t SZ = (size_t)MDIM * NDIM;
    float* gh = fbase;

    unsigned short* hs = abase;
    unsigned short* gx = abase + SZ;
    unsigned short* y1 = abase + 2 * SZ;
    unsigned short* y2 = abase + 3 * SZ;
    unsigned short* ks = abase + 4 * SZ;

    const size_t WSZ = (size_t)KDIM * NDIM;
    unsigned short* w1x = wbase;
    unsigned short* w2x = wbase + WSZ;
    unsigned short* w3x = wbase + 2 * WSZ;

    {
        dim3 g(NDIM / 32, KDIM / 32), b(32, 8);
        wsplit_kernel<<<g, b>>>(W1, w1x);
        wsplit_kernel<<<g, b>>>(W2, w2x);
        wsplit_kernel<<<g, b>>>(W3, w3x);
        asplit_kernel<<<(int)(SZ / 4 / 256), 256>>>(h0, hs);
    }

    const float dt = 0.1f;
    const float* trow = W1 + (size_t)KDIM * NDIM;

    int edge = 0;  // GEMM index in the 120-long chain
#define FLAG_IN  ((edge == 0) ? (const int*)nullptr : (const int*)(flbase + (edge - 1) * NRB))
#define FLAG_OUT ((edge < 119) ? (flbase + edge * NRB) : (int*)nullptr)

    for (int s = 0; s < STEPS_N; s++) {
        const float t0 = dt * (float)s;
        const float* hin = (s == 0) ? h0 : gh;
        float* hdst = (s == STEPS_N - 1) ? out : gh;

        // k1 = f(t0, h)
        launch_gemm<EPI_TANH>(hs, w1x, b1, trow, t0, y1, nullptr, nullptr, nullptr, nullptr, 0.f, FLAG_IN, FLAG_OUT); edge++;
        launch_gemm<EPI_TANH>(y1, w2x, b2, nullptr, 0.f, y2, nullptr, nullptr, nullptr, nullptr, 0.f, FLAG_IN, FLAG_OUT); edge++;
        launch_gemm<EPI_K1>(y2, w3x, b3, nullptr, 0.f, gx, nullptr, hs, ks, nullptr, dt * 0.5f, FLAG_IN, FLAG_OUT); edge++;
        // k2 = f(t0+dt/2, h + dt/2*k1)
        launch_gemm<EPI_TANH>(gx, w1x, b1, trow, t0 + dt * 0.5f, y1, nullptr, nullptr, nullptr, nullptr, 0.f, FLAG_IN, FLAG_OUT); edge++;
        launch_gemm<EPI_TANH>(y1, w2x, b2, nullptr, 0.f, y2, nullptr, nullptr, nullptr, nullptr, 0.f, FLAG_IN, FLAG_OUT); edge++;
        launch_gemm<EPI_KMID>(y2, w3x, b3, nullptr, 0.f, gx, nullptr, hs, ks, nullptr, dt * 0.5f, FLAG_IN, FLAG_OUT); edge++;
        // k3 = f(t0+dt/2, h + dt/2*k2)
        launch_gemm<EPI_TANH>(gx, w1x, b1, trow, t0 + dt * 0.5f, y1, nullptr, nullptr, nullptr, nullptr, 0.f, FLAG_IN, FLAG_OUT); edge++;
        launch_gemm<EPI_TANH>(y1, w2x, b2, nullptr, 0.f, y2, nullptr, nullptr, nullptr, nullptr, 0.f, FLAG_IN, FLAG_OUT); edge++;
        launch_gemm<EPI_KMID>(y2, w3x, b3, nullptr, 0.f, gx, nullptr, hs, ks, nullptr, dt, FLAG_IN, FLAG_OUT); edge++;
        // k4 = f(t0+dt, h + dt*k3); h' = h + dt/6*(ksum + k4)
        launch_gemm<EPI_TANH>(gx, w1x, b1, trow, t0 + dt, y1, nullptr, nullptr, nullptr, nullptr, 0.f, FLAG_IN, FLAG_OUT); edge++;
        launch_gemm<EPI_TANH>(y1, w2x, b2, nullptr, 0.f, y2, nullptr, nullptr, nullptr, nullptr, 0.f, FLAG_IN, FLAG_OUT); edge++;
        launch_gemm<EPI_K4>(y2, w3x, b3, nullptr, 0.f, hs, hin, nullptr, ks, hdst, dt / 6.0f, FLAG_IN, FLAG_OUT); edge++;
    }
#undef FLAG_IN
#undef FLAG_OUT
}

// round 16
// speedup vs baseline: 1.6553x; 1.2169x over previous
#include <cuda_runtime.h>
#include <cuda_fp16.h>
#include <math.h>
#include <stddef.h>
#include <stdint.h>

// ---------------------------------------------------------------------------
// NeuralODE, algebraically fused: 9 GEMMs/step instead of 12.
//   W31 = W3 @ W1'  (precomputed once, fp16), bW31 = b3 @ W1'.
//   Per step: hW1 = h@W1' (fp32, reused by all 4 evals);
//   layer-1 of evals 2-4:  z = hW1 + c*(y2@W31) + c*bW31 + b1 + t*trow;
//   h' = h + dt/6*(ysum@W3) + dt*b3,  ysum = y2_1+2y2_2+2y2_3+y2_4
//   (accumulated in layer-2 epilogues).
// GEMM core: fp16 mma.sync, 128x128 CTA tile, 8 warps, BK=64, NBUF=3,
// 2 CTAs/SM, PDL + per-rowblock cross-kernel flags (R15 pipeline).
// ---------------------------------------------------------------------------

#define MDIM 8192
#define NDIM 1024
#define KDIM 1024
#define STEPS_N 10

enum EpiMode { EPI_HW1 = 0, EPI_L2 = 1, EPI_L1MID = 2, EPI_FIN = 3, EPI_STORE = 4 };

constexpr int BM = 128, BN = 128, BK = 64;
constexpr int NT = 256;
constexpr int NSTAGES = KDIM / BK;  // 16
constexpr int NBUF = 3;
constexpr int NRB = MDIM / BM;      // 64 rowblocks
constexpr int NPROD = NDIM / BN;    // 8 producer tiles per rowblock
constexpr int NEDGES = 90;          // 9 GEMMs x 10 steps

constexpr int RSB = 144;            // 16*9: conflict-free ldmatrix
constexpr int TILE_B = 128 * RSB;          // 18432
constexpr int T_A = 0, T_B = TILE_B;
constexpr int STAGE_B = 2 * TILE_B;        // 36864
constexpr int SMEM_TOTAL = NBUF * STAGE_B; // 110592 (2 CTAs -> 221KB/SM)

// ---- global scratch ------------------------------------------------------
__device__ float g_f32[2ull * MDIM * NDIM];           // gh, hw1
__device__ unsigned short g_bf[4ull * MDIM * NDIM];   // hs, y1, y2, ysum
__device__ unsigned short g_wt[5ull * KDIM * NDIM];   // w1x,w2x,w3x,w31x,w3row
__device__ float g_vec[NDIM];                         // bW31
__device__ int g_flags[NEDGES * NRB];                 // rowblock readiness

// ---- PTX helpers ---------------------------------------------------------

__device__ __forceinline__ uint32_t smem_to_u32(const void* p) {
    uint32_t a;
    asm("{ .reg .u64 t; cvta.to.shared.u64 t, %1; cvt.u32.u64 %0, t; }"
        : "=r"(a) : "l"(p));
    return a;
}

#define CP_ASYNC16(saddr, gptr)                                   \
    asm volatile("cp.async.cg.shared.global [%0], [%1], 16;" ::   \
                     "r"(saddr), "l"(gptr))
#define CP_COMMIT() asm volatile("cp.async.commit_group;" ::: "memory")
#define CP_WAIT1() asm volatile("cp.async.wait_group 1;" ::: "memory")
#define CP_WAIT0() asm volatile("cp.async.wait_group 0;" ::: "memory")

#define GRIDDEP_WAIT() asm volatile("griddepcontrol.wait;" ::: "memory")
#define GRIDDEP_LAUNCH() \
    asm volatile("griddepcontrol.launch_dependents;" ::: "memory")

#define LDSM_X4(r0, r1, r2, r3, addr)                                     \
    asm volatile("ldmatrix.sync.aligned.m8n8.x4.shared.b16 "              \
                 "{%0,%1,%2,%3}, [%4];"                                   \
                 : "=r"(r0), "=r"(r1), "=r"(r2), "=r"(r3) : "r"(addr))

#define MMA_F16(D, A, B)                                                   \
    asm volatile("mma.sync.aligned.m16n8k16.row.col.f32.f16.f16.f32 "      \
                 "{%0,%1,%2,%3}, {%4,%5,%6,%7}, {%8,%9}, {%0,%1,%2,%3};"   \
                 : "+f"((D)[0]), "+f"((D)[1]), "+f"((D)[2]), "+f"((D)[3])  \
                 : "r"((A)[0]), "r"((A)[1]), "r"((A)[2]), "r"((A)[3]),     \
                   "r"((B)[0]), "r"((B)[1]))

__device__ __forceinline__ float fast_tanh(float x) {
    float r;
    asm("tanh.approx.f32 %0, %1;" : "=f"(r) : "f"(x));
    return r;
}

__device__ __forceinline__ float4 ld4(const float* p) { return *(const float4*)p; }

__device__ __forceinline__ uint32_t pack_h2(float a, float b) {
    __half2 h = __floats2half2_rn(a, b);
    return *(uint32_t*)&h;
}

__device__ __forceinline__ float2 unpack_h2(uint32_t u) {
    __half2 h = *(__half2*)&u;
    return __half22float2(h);
}

// ---- weight convert+transpose: out[n][k] = fp16(W[k][n]) -----------------

__global__ void wsplit_kernel(const float* __restrict__ W,
                              unsigned short* __restrict__ hi) {
    __shared__ float t[32][33];
    const int tx = threadIdx.x, ty = threadIdx.y;
    const int n0 = blockIdx.x * 32, k0 = blockIdx.y * 32;
#pragma unroll
    for (int j = 0; j < 32; j += 8)
        t[ty + j][tx] = W[(size_t)(k0 + ty + j) * NDIM + n0 + tx];
    __syncthreads();
#pragma unroll
    for (int j = 0; j < 32; j += 8) {
        float v = t[tx][ty + j];
        __half h = __float2half_rn(v);
        hi[(size_t)(n0 + ty + j) * KDIM + k0 + tx] = *(unsigned short*)&h;
    }
}

// ---- elementwise fp32 -> fp16 ---------------------------------------------

__global__ void asplit_kernel(const float* __restrict__ X,
                              unsigned short* __restrict__ hi) {
    size_t i = ((size_t)blockIdx.x * blockDim.x + threadIdx.x) * 4;
    float4 v = ld4(X + i);
    *(uint2*)(hi + i) = make_uint2(pack_h2(v.x, v.y), pack_h2(v.z, v.w));
}

// ---- bW31[n] = sum_j b3[j] * W1[j][n] -------------------------------------

__global__ void bw31_kernel(const float* __restrict__ b3,
                            const float* __restrict__ W1,
                            float* __restrict__ outv) {
    const int n = blockIdx.x * blockDim.x + threadIdx.x;
    float s = 0.f;
    for (int j = 0; j < NDIM; ++j)
        s = fmaf(b3[j], W1[(size_t)j * NDIM + n], s);
    outv[n] = s;
}

// ---- fused epilogue per (row, col-pair) ------------------------------------

template <int EPI>
__device__ __forceinline__ void epi_rc(int m, int c, float a0, float a1,
                                       float bb0, float bb1,
                                       unsigned short* oh, float* hw1,
                                       const float* hbase,
                                       unsigned short* ysum,
                                       float* hout, float coef, float kc) {
    const size_t idx = (size_t)m * NDIM + c;
    if (EPI == EPI_HW1) {
        *(float2*)(hw1 + idx) = make_float2(a0, a1);          // raw h@W1'
        *(uint32_t*)(oh + idx) =
            pack_h2(fast_tanh(a0 + bb0), fast_tanh(a1 + bb1));  // y1 of eval1
    } else if (EPI == EPI_L2) {
        float y0 = fast_tanh(a0 + bb0), y1v = fast_tanh(a1 + bb1);
        *(uint32_t*)(oh + idx) = pack_h2(y0, y1v);
        if (kc == 0.f) {
            *(uint32_t*)(ysum + idx) = pack_h2(y0, y1v);
        } else {
            float2 s = unpack_h2(*(uint32_t*)(ysum + idx));
            s.x = fmaf(kc, y0, s.x);
            s.y = fmaf(kc, y1v, s.y);
            *(uint32_t*)(ysum + idx) = pack_h2(s.x, s.y);
        }
    } else if (EPI == EPI_L1MID) {
        float2 h2 = *(const float2*)(hw1 + idx);
        float z0 = fmaf(coef, a0, h2.x) + bb0;
        float z1 = fmaf(coef, a1, h2.y) + bb1;
        *(uint32_t*)(oh + idx) = pack_h2(fast_tanh(z0), fast_tanh(z1));
    } else if (EPI == EPI_FIN) {
        float2 h = *(const float2*)(hbase + idx);
        float g0 = fmaf(coef, a0, h.x) + bb0;   // bb = dt*b3
        float g1 = fmaf(coef, a1, h.y) + bb1;
        *(float2*)(hout + idx) = make_float2(g0, g1);
        *(uint32_t*)(oh + idx) = pack_h2(g0, g1);  // hs for next step
    } else {  // EPI_STORE (prep: raw fp16 store)
        *(uint32_t*)(oh + idx) = pack_h2(a0, a1);
    }
}

// ---- main GEMM --------------------------------------------------------------

template <int EPI>
__global__ void __launch_bounds__(NT, 2)
ngemm_kernel(const unsigned short* __restrict__ Ax,
             const unsigned short* __restrict__ Bx,
             const float* __restrict__ bias,
             const float* __restrict__ trow, float tval,
             const float* __restrict__ bw31,
             unsigned short* __restrict__ oh,
             float* __restrict__ hw1,
             const float* __restrict__ hbase,
             unsigned short* __restrict__ ysum,
             float* __restrict__ hout, float coef, float kc,
             const int* flag_in, int* flag_out) {
    extern __shared__ char smc[];
    const uint32_t sb = smem_to_u32(smc);
    const int tid = threadIdx.x;
    const int lane = tid & 31;
    const int w = tid >> 5;
    const int wm = w & 1;
    const int wn = w >> 1;
    const int bm = blockIdx.y * BM;
    const int bn = blockIdx.x * BN;

    const int cr = tid >> 3;
    const int cc = (tid & 7) * 8;
    const unsigned short* gaP[4];
    const unsigned short* gbP[4];
    uint32_t scP[4];
#pragma unroll
    for (int k = 0; k < 4; ++k) {
        const int row = k * 32 + cr;
        gaP[k] = Ax + (size_t)(bm + row) * KDIM + cc;
        gbP[k] = Bx + (size_t)(bn + row) * KDIM + cc;
        scP[k] = (uint32_t)(row * RSB + (tid & 7) * 16);
    }

    const uint32_t a_off = (uint32_t)((lane & 15) * RSB + ((lane & 16) ? 16 : 0));
    const uint32_t b_off = (uint32_t)(((lane & 7) + ((lane & 16) ? 8 : 0)) * RSB +
                                      ((lane & 8) ? 16 : 0));

    float acc[4][4][4];
#pragma unroll
    for (int i = 0; i < 4; i++)
#pragma unroll
        for (int j = 0; j < 4; j++)
#pragma unroll
            for (int q = 0; q < 4; q++) acc[i][j][q] = 0.f;

    // ---- B (weights) prefetch for stages 0,1: no data dependency.
#pragma unroll
    for (int k = 0; k < 4; ++k) {
        CP_ASYNC16(sb + 0 * STAGE_B + T_B + scP[k], gbP[k]);
        CP_ASYNC16(sb + 1 * STAGE_B + T_B + scP[k], gbP[k] + BK);
    }

    if (EPI != EPI_STORE) {
        GRIDDEP_LAUNCH();  // successors self-protect via rowblock flags
        if (flag_in != nullptr) {
            if (tid == 0) {
                volatile int* fi = (volatile int*)(flag_in + blockIdx.y);
                while (*fi < NPROD) __nanosleep(64);
                __threadfence();  // acquire
                int old = atomicAdd((int*)(flag_in + blockIdx.y), 1);
                if (old == 2 * NPROD - 1)
                    atomicExch((int*)(flag_in + blockIdx.y), 0);
            }
            __syncthreads();
        } else {
            GRIDDEP_WAIT();  // first chain kernel: wait prep completion
        }
    }

    // A prologue loads. Groups: g0 = {8x B prefetch, A0}, g1 = {A1}.
#pragma unroll
    for (int k = 0; k < 4; ++k)
        CP_ASYNC16(sb + 0 * STAGE_B + T_A + scP[k], gaP[k]);
    CP_COMMIT();
#pragma unroll
    for (int k = 0; k < 4; ++k)
        CP_ASYNC16(sb + 1 * STAGE_B + T_A + scP[k], gaP[k] + BK);
    CP_COMMIT();

#define ISSUE_STAGE(st)                                                   \
    do {                                                                  \
        const int _kc = (st) * BK;                                        \
        const uint32_t _b = sb + ((st) % NBUF) * STAGE_B;                 \
        _Pragma("unroll")                                                 \
        for (int _k = 0; _k < 4; ++_k) {                                  \
            CP_ASYNC16(_b + T_A + scP[_k], gaP[_k] + _kc);                \
            CP_ASYNC16(_b + T_B + scP[_k], gbP[_k] + _kc);                \
        }                                                                 \
        CP_COMMIT();                                                      \
    } while (0)

#pragma unroll 1
    for (int s = 0; s < NSTAGES; ++s) {
        if (s + 1 < NSTAGES) {
            CP_WAIT1();
        } else {
            CP_WAIT0();
        }
        __syncthreads();
        if (s + 2 < NSTAGES) ISSUE_STAGE(s + 2);

        const uint32_t base = sb + (s % NBUF) * STAGE_B;
#pragma unroll
        for (int ks = 0; ks < 4; ++ks) {
            uint32_t a_[4][4], b_[4][2];
#pragma unroll
            for (int i = 0; i < 4; ++i) {
                const uint32_t ra =
                    base + (uint32_t)((wm * 64 + i * 16) * RSB + ks * 32) + a_off;
                LDSM_X4(a_[i][0], a_[i][1], a_[i][2], a_[i][3], ra + T_A);
            }
#pragma unroll
            for (int jj = 0; jj < 2; ++jj) {
                const uint32_t rb =
                    base + (uint32_t)((wn * 32 + jj * 16) * RSB + ks * 32) + b_off;
                uint32_t t0, t1, t2, t3;
                LDSM_X4(t0, t1, t2, t3, rb + T_B);
                b_[2 * jj][0] = t0; b_[2 * jj][1] = t1;
                b_[2 * jj + 1][0] = t2; b_[2 * jj + 1][1] = t3;
            }
#pragma unroll
            for (int i = 0; i < 4; ++i)
#pragma unroll
                for (int j = 0; j < 4; ++j) {
                    MMA_F16(acc[i][j], a_[i], b_[j]);
                }
        }
    }
#undef ISSUE_STAGE

    // ---------------- epilogue -------------------------------------------
#pragma unroll
    for (int j = 0; j < 4; ++j) {
        const int c = bn + wn * 32 + j * 8 + (lane & 3) * 2;
        float bb0 = 0.f, bb1 = 0.f;
        if (EPI != EPI_STORE) {
            bb0 = bias[c];
            bb1 = bias[c + 1];
        }
        if (EPI == EPI_FIN) {
            bb0 *= kc;  // dt * b3
            bb1 *= kc;
        }
        if ((EPI == EPI_HW1 || EPI == EPI_L1MID) && trow != nullptr) {
            bb0 = fmaf(tval, trow[c], bb0);
            bb1 = fmaf(tval, trow[c + 1], bb1);
        }
        if (EPI == EPI_L1MID) {
            bb0 = fmaf(coef, bw31[c], bb0);
            bb1 = fmaf(coef, bw31[c + 1], bb1);
        }
#pragma unroll
        for (int i = 0; i < 4; ++i) {
            const int m0 = bm + wm * 64 + i * 16 + (lane >> 2);
            epi_rc<EPI>(m0, c, acc[i][j][0], acc[i][j][1], bb0, bb1,
                        oh, hw1, hbase, ysum, hout, coef, kc);
            epi_rc<EPI>(m0 + 8, c, acc[i][j][2], acc[i][j][3], bb0, bb1,
                        oh, hw1, hbase, ysum, hout, coef, kc);
        }
    }

    if (EPI != EPI_STORE && flag_out != nullptr) {
        __syncthreads();
        if (tid == 0) {
            __threadfence();  // release
            atomicAdd(flag_out + blockIdx.y, 1);
        }
    }
}

// ---------------------------------------------------------------------------

template <int EPI>
static inline void launch_gemm(const unsigned short* Ax, const unsigned short* Bx,
                               const float* bias, const float* trow, float tval,
                               const float* bw31, unsigned short* oh,
                               float* hw1, const float* hbase,
                               unsigned short* ysum, float* hout,
                               float coef, float kc,
                               const int* flag_in, int* flag_out) {
    cudaLaunchConfig_t cfg = {};
    cfg.gridDim = dim3(NDIM / BN, MDIM / BM);
    cfg.blockDim = dim3(NT);
    cfg.dynamicSmemBytes = SMEM_TOTAL;
    cfg.stream = 0;
    cudaLaunchAttribute attr[1];
    attr[0].id = cudaLaunchAttributeProgrammaticStreamSerialization;
    attr[0].val.programmaticStreamSerializationAllowed = 1;
    cfg.attrs = attr;
    cfg.numAttrs = 1;
    cudaLaunchKernelEx(&cfg, ngemm_kernel<EPI>, Ax, Bx, bias, trow, tval,
                       bw31, oh, hw1, hbase, ysum, hout, coef, kc,
                       flag_in, flag_out);
}

extern "C" void kernel_launch(void* const* d_in, const int* in_sizes, int n_in,
                              void* d_out, int out_size) {
    const float* h0 = (const float*)d_in[0];
    const float* W1 = (const float*)d_in[1];
    const float* b1 = (const float*)d_in[2];
    const float* W2 = (const float*)d_in[3];
    const float* b2 = (const float*)d_in[4];
    const float* W3 = (const float*)d_in[5];
    const float* b3 = (const float*)d_in[6];
    float* out = (float*)d_out;

    cudaFuncSetAttribute(ngemm_kernel<EPI_HW1>,
                         cudaFuncAttributeMaxDynamicSharedMemorySize, SMEM_TOTAL);
    cudaFuncSetAttribute(ngemm_kernel<EPI_L2>,
                         cudaFuncAttributeMaxDynamicSharedMemorySize, SMEM_TOTAL);
    cudaFuncSetAttribute(ngemm_kernel<EPI_L1MID>,
                         cudaFuncAttributeMaxDynamicSharedMemorySize, SMEM_TOTAL);
    cudaFuncSetAttribute(ngemm_kernel<EPI_FIN>,
                         cudaFuncAttributeMaxDynamicSharedMemorySize, SMEM_TOTAL);
    cudaFuncSetAttribute(ngemm_kernel<EPI_STORE>,
                         cudaFuncAttributeMaxDynamicSharedMemorySize, SMEM_TOTAL);

    float* fbase = nullptr;
    cudaGetSymbolAddress((void**)&fbase, g_f32);
    unsigned short* abase = nullptr;
    cudaGetSymbolAddress((void**)&abase, g_bf);
    unsigned short* wbase = nullptr;
    cudaGetSymbolAddress((void**)&wbase, g_wt);
    float* vbase = nullptr;
    cudaGetSymbolAddress((void**)&vbase, g_vec);
    int* flbase = nullptr;
    cudaGetSymbolAddress((void**)&flbase, g_flags);

    const size_t SZ = (size_t)MDIM * NDIM;
    float* gh = fbase;              // carried fp32 state
    float* hw1 = fbase + SZ;        // h @ W1' (fp32, per step)

    unsigned short* hs = abase;             // fp16 h snapshot
    unsigned short* y1 = abase + SZ;
    unsigned short* y2 = abase + 2 * SZ;
    unsigned short* ys = abase + 3 * SZ;    // ysum fp16

    const size_t WSZ = (size_t)KDIM * NDIM;
    unsigned short* w1x = wbase;
    unsigned short* w2x = wbase + WSZ;
    unsigned short* w3x = wbase + 2 * WSZ;
    unsigned short* w31x = wbase + 3 * WSZ;
    unsigned short* w3row = wbase + 4 * WSZ;  // fp16(W3) row-major
    float* bw31 = vbase;

    // ---- one-time prep ----------------------------------------------------
    {
        dim3 g(NDIM / 32, KDIM / 32), b(32, 8);
        wsplit_kernel<<<g, b>>>(W1, w1x);
        wsplit_kernel<<<g, b>>>(W2, w2x);
        wsplit_kernel<<<g, b>>>(W3, w3x);
        asplit_kernel<<<(int)(SZ / 4 / 256), 256>>>(h0, hs);
        asplit_kernel<<<(int)(WSZ / 4 / 256), 256>>>(W3, w3row);
        bw31_kernel<<<NDIM / 256, 256>>>(b3, W1, bw31);
        // W31^T[n][i] = sum_j W1[j][n]*W3[i][j]:
        //   A = w1x (row-major [n][j] = W1^T), B = w3row ([i][j] K-major).
        // Plain launch (no PDL): the chain must not prefetch w31x early.
        ngemm_kernel<EPI_STORE><<<dim3(NDIM / BN, NDIM / BM), NT, SMEM_TOTAL>>>(
            w1x, w3row, nullptr, nullptr, 0.f, nullptr, w31x, nullptr,
            nullptr, nullptr, nullptr, 0.f, 0.f, nullptr, nullptr);
    }

    const float dt = 0.1f;
    const float* trow = W1 + (size_t)KDIM * NDIM;  // W1 row 1024 (t row)

    int edge = 0;
#define FLAG_IN  ((edge == 0) ? (const int*)nullptr : (const int*)(flbase + (edge - 1) * NRB))
#define FLAG_OUT ((edge < NEDGES - 1) ? (flbase + edge * NRB) : (int*)nullptr)

    for (int s = 0; s < STEPS_N; s++) {
        const float t0 = dt * (float)s;
        const float* hin = (s == 0) ? h0 : gh;
        float* hdst = (s == STEPS_N - 1) ? out : gh;

        // hW1 = h@W1' (fp32) ; y1_1 = tanh(hW1 + b1 + t0*trow)
        launch_gemm<EPI_HW1>(hs, w1x, b1, trow, t0, nullptr, y1, hw1,
                             nullptr, nullptr, nullptr, 0.f, 0.f,
                             FLAG_IN, FLAG_OUT); edge++;
        // y2_1 = tanh(y1@W2 + b2) ; ysum = y2_1
        launch_gemm<EPI_L2>(y1, w2x, b2, nullptr, 0.f, nullptr, y2, nullptr,
                            nullptr, ys, nullptr, 0.f, 0.f,
                            FLAG_IN, FLAG_OUT); edge++;
        // eval2 layer1: z = hW1 + (dt/2)*(y2@W31 + bW31) + b1 + t*trow
        launch_gemm<EPI_L1MID>(y2, w31x, b1, trow, t0 + dt * 0.5f, bw31, y1,
                               hw1, nullptr, nullptr, nullptr, dt * 0.5f, 0.f,
                               FLAG_IN, FLAG_OUT); edge++;
        // y2_2 ; ysum += 2*y2_2
        launch_gemm<EPI_L2>(y1, w2x, b2, nullptr, 0.f, nullptr, y2, nullptr,
                            nullptr, ys, nullptr, 0.f, 2.f,
                            FLAG_IN, FLAG_OUT); edge++;
        // eval3 layer1 (coef dt/2)
        launch_gemm<EPI_L1MID>(y2, w31x, b1, trow, t0 + dt * 0.5f, bw31, y1,
                               hw1, nullptr, nullptr, nullptr, dt * 0.5f, 0.f,
                               FLAG_IN, FLAG_OUT); edge++;
        // y2_3 ; ysum += 2*y2_3
        launch_gemm<EPI_L2>(y1, w2x, b2, nullptr, 0.f, nullptr, y2, nullptr,
                            nullptr, ys, nullptr, 0.f, 2.f,
                            FLAG_IN, FLAG_OUT); edge++;
        // eval4 layer1 (coef dt)
        launch_gemm<EPI_L1MID>(y2, w31x, b1, trow, t0 + dt, bw31, y1,
                               hw1, nullptr, nullptr, nullptr, dt, 0.f,
                               FLAG_IN, FLAG_OUT); edge++;
        // y2_4 ; ysum += y2_4
        launch_gemm<EPI_L2>(y1, w2x, b2, nullptr, 0.f, nullptr, y2, nullptr,
                            nullptr, ys, nullptr, 0.f, 1.f,
                            FLAG_IN, FLAG_OUT); edge++;
        // h' = h + dt/6*(ysum@W3) + dt*b3 ; hs = fp16(h')
        launch_gemm<EPI_FIN>(ys, w3x, b3, nullptr, 0.f, nullptr, hs, nullptr,
                             hin, nullptr, hdst, dt / 6.0f, dt,
                             FLAG_IN, FLAG_OUT); edge++;
    }
#undef FLAG_IN
#undef FLAG_OUT
}

// round 17
// speedup vs baseline: 1.7402x; 1.0513x over previous
#include <cuda_runtime.h>
#include <cuda_fp16.h>
#include <math.h>
#include <stddef.h>
#include <stdint.h>

// ---------------------------------------------------------------------------
// NeuralODE, fully linear-fused: 8 GEMMs/step (82 total).
//   Carry hW1 = h@W1' (fp32) instead of h:
//     step end:  hW1 += (dt/6)*(ysum@W31) + dt*bW31   (one GEMM)
//                S   += ysum (fp16 accumulator, in the same epilogue)
//                y1(next eval1) = tanh(hW1' + b1 + t_next*trow)  (free)
//   h only materialized once at the end:
//     h_final = h0 + (dt/6)*(S@W3) + 10*dt*b3        (one GEMM)
//   W31 = W3@W1', bW31 = b3@W1' precomputed.
// GEMM core: fp16 mma.sync, 128x128 CTA tile, 8 warps, BK=64, NBUF=3,
// 2 CTAs/SM, PDL + per-rowblock cross-kernel flags (R15/R16 pipeline).
// ---------------------------------------------------------------------------

#define MDIM 8192
#define NDIM 1024
#define KDIM 1024
#define STEPS_N 10

enum EpiMode { EPI_HW1 = 0, EPI_L2 = 1, EPI_L1MID = 2, EPI_STEPEND = 3,
               EPI_FINAL = 4, EPI_STORE = 5 };

constexpr int BM = 128, BN = 128, BK = 64;
constexpr int NT = 256;
constexpr int NSTAGES = KDIM / BK;  // 16
constexpr int NBUF = 3;
constexpr int NRB = MDIM / BM;      // 64 rowblocks
constexpr int NPROD = NDIM / BN;    // 8 producer tiles per rowblock
constexpr int NEDGES = 82;          // 1 + 10*8 + 1

constexpr int RSB = 144;            // 16*9: conflict-free ldmatrix
constexpr int TILE_B = 128 * RSB;          // 18432
constexpr int T_A = 0, T_B = TILE_B;
constexpr int STAGE_B = 2 * TILE_B;        // 36864
constexpr int SMEM_TOTAL = NBUF * STAGE_B; // 110592 (2 CTAs -> 221KB/SM)

// ---- global scratch ------------------------------------------------------
__device__ float g_f32[1ull * MDIM * NDIM];           // hw1 (fp32 carried)
__device__ unsigned short g_bf[5ull * MDIM * NDIM];   // hs, y1, y2, ysum, S
__device__ unsigned short g_wt[5ull * KDIM * NDIM];   // w1x,w2x,w3x,w31x,w3row
__device__ float g_vec[NDIM];                         // bW31
__device__ int g_flags[NEDGES * NRB];                 // rowblock readiness

// ---- PTX helpers ---------------------------------------------------------

__device__ __forceinline__ uint32_t smem_to_u32(const void* p) {
    uint32_t a;
    asm("{ .reg .u64 t; cvta.to.shared.u64 t, %1; cvt.u32.u64 %0, t; }"
        : "=r"(a) : "l"(p));
    return a;
}

#define CP_ASYNC16(saddr, gptr)                                   \
    asm volatile("cp.async.cg.shared.global [%0], [%1], 16;" ::   \
                     "r"(saddr), "l"(gptr))
#define CP_COMMIT() asm volatile("cp.async.commit_group;" ::: "memory")
#define CP_WAIT1() asm volatile("cp.async.wait_group 1;" ::: "memory")
#define CP_WAIT0() asm volatile("cp.async.wait_group 0;" ::: "memory")

#define GRIDDEP_WAIT() asm volatile("griddepcontrol.wait;" ::: "memory")
#define GRIDDEP_LAUNCH() \
    asm volatile("griddepcontrol.launch_dependents;" ::: "memory")

#define LDSM_X4(r0, r1, r2, r3, addr)                                     \
    asm volatile("ldmatrix.sync.aligned.m8n8.x4.shared.b16 "              \
                 "{%0,%1,%2,%3}, [%4];"                                   \
                 : "=r"(r0), "=r"(r1), "=r"(r2), "=r"(r3) : "r"(addr))

#define MMA_F16(D, A, B)                                                   \
    asm volatile("mma.sync.aligned.m16n8k16.row.col.f32.f16.f16.f32 "      \
                 "{%0,%1,%2,%3}, {%4,%5,%6,%7}, {%8,%9}, {%0,%1,%2,%3};"   \
                 : "+f"((D)[0]), "+f"((D)[1]), "+f"((D)[2]), "+f"((D)[3])  \
                 : "r"((A)[0]), "r"((A)[1]), "r"((A)[2]), "r"((A)[3]),     \
                   "r"((B)[0]), "r"((B)[1]))

__device__ __forceinline__ float fast_tanh(float x) {
    float r;
    asm("tanh.approx.f32 %0, %1;" : "=f"(r) : "f"(x));
    return r;
}

__device__ __forceinline__ float4 ld4(const float* p) { return *(const float4*)p; }

__device__ __forceinline__ uint32_t pack_h2(float a, float b) {
    __half2 h = __floats2half2_rn(a, b);
    return *(uint32_t*)&h;
}

__device__ __forceinline__ float2 unpack_h2(uint32_t u) {
    __half2 h = *(__half2*)&u;
    return __half22float2(h);
}

// ---- weight convert+transpose: out[n][k] = fp16(W[k][n]) -----------------

__global__ void wsplit_kernel(const float* __restrict__ W,
                              unsigned short* __restrict__ hi) {
    __shared__ float t[32][33];
    const int tx = threadIdx.x, ty = threadIdx.y;
    const int n0 = blockIdx.x * 32, k0 = blockIdx.y * 32;
#pragma unroll
    for (int j = 0; j < 32; j += 8)
        t[ty + j][tx] = W[(size_t)(k0 + ty + j) * NDIM + n0 + tx];
    __syncthreads();
#pragma unroll
    for (int j = 0; j < 32; j += 8) {
        float v = t[tx][ty + j];
        __half h = __float2half_rn(v);
        hi[(size_t)(n0 + ty + j) * KDIM + k0 + tx] = *(unsigned short*)&h;
    }
}

// ---- elementwise fp32 -> fp16 ---------------------------------------------

__global__ void asplit_kernel(const float* __restrict__ X,
                              unsigned short* __restrict__ hi) {
    size_t i = ((size_t)blockIdx.x * blockDim.x + threadIdx.x) * 4;
    float4 v = ld4(X + i);
    *(uint2*)(hi + i) = make_uint2(pack_h2(v.x, v.y), pack_h2(v.z, v.w));
}

// ---- bW31[n] = sum_j b3[j] * W1[j][n] -------------------------------------

__global__ void bw31_kernel(const float* __restrict__ b3,
                            const float* __restrict__ W1,
                            float* __restrict__ outv) {
    const int n = blockIdx.x * blockDim.x + threadIdx.x;
    float s = 0.f;
    for (int j = 0; j < NDIM; ++j)
        s = fmaf(b3[j], W1[(size_t)j * NDIM + n], s);
    outv[n] = s;
}

// ---- fused epilogue per (row, col-pair) ------------------------------------
// bb = primary per-column bias; cc = secondary (STEPEND: dt*bW31).

template <int EPI>
__device__ __forceinline__ void epi_rc(int m, int c, float a0, float a1,
                                       float bb0, float bb1,
                                       float cc0, float cc1,
                                       unsigned short* oh, float* hw1,
                                       const float* hbase,
                                       const unsigned short* ysum,
                                       unsigned short* Sbuf,
                                       float* hout, float coef, float kc) {
    const size_t idx = (size_t)m * NDIM + c;
    if (EPI == EPI_HW1) {
        *(float2*)(hw1 + idx) = make_float2(a0, a1);          // raw h0@W1'
        *(uint32_t*)(oh + idx) =
            pack_h2(fast_tanh(a0 + bb0), fast_tanh(a1 + bb1));  // y1 eval1
    } else if (EPI == EPI_L2) {
        float y0 = fast_tanh(a0 + bb0), y1v = fast_tanh(a1 + bb1);
        *(uint32_t*)(oh + idx) = pack_h2(y0, y1v);
        if (kc == 0.f) {
            *(uint32_t*)(Sbuf + idx) = pack_h2(y0, y1v);  // Sbuf = ysum here
        } else {
            float2 s = unpack_h2(*(uint32_t*)(Sbuf + idx));
            s.x = fmaf(kc, y0, s.x);
            s.y = fmaf(kc, y1v, s.y);
            *(uint32_t*)(Sbuf + idx) = pack_h2(s.x, s.y);
        }
    } else if (EPI == EPI_L1MID) {
        float2 h2 = *(const float2*)(hw1 + idx);
        float z0 = fmaf(coef, a0, h2.x) + bb0;
        float z1 = fmaf(coef, a1, h2.y) + bb1;
        *(uint32_t*)(oh + idx) = pack_h2(fast_tanh(z0), fast_tanh(z1));
    } else if (EPI == EPI_STEPEND) {
        // hW1' = hW1 + coef*(ysum@W31) + dt*bW31
        float2 h2 = *(const float2*)(hw1 + idx);
        float hn0 = fmaf(coef, a0, h2.x) + cc0;
        float hn1 = fmaf(coef, a1, h2.y) + cc1;
        *(float2*)(hw1 + idx) = make_float2(hn0, hn1);
        // S += ysum (fp16 accumulator; kc==0 -> first step stores fresh)
        float2 yv = unpack_h2(*(const uint32_t*)(ysum + idx));
        if (kc == 0.f) {
            *(uint32_t*)(Sbuf + idx) = pack_h2(yv.x, yv.y);
        } else {
            float2 s = unpack_h2(*(uint32_t*)(Sbuf + idx));
            *(uint32_t*)(Sbuf + idx) = pack_h2(s.x + yv.x, s.y + yv.y);
        }
        // y1 for next step's eval1
        *(uint32_t*)(oh + idx) =
            pack_h2(fast_tanh(hn0 + bb0), fast_tanh(hn1 + bb1));
    } else if (EPI == EPI_FINAL) {
        float2 h = *(const float2*)(hbase + idx);   // h0 (fp32 input)
        float g0 = fmaf(coef, a0, h.x) + bb0;       // bb = 10*dt*b3 = b3
        float g1 = fmaf(coef, a1, h.y) + bb1;
        *(float2*)(hout + idx) = make_float2(g0, g1);
    } else {  // EPI_STORE (prep: raw fp16 store)
        *(uint32_t*)(oh + idx) = pack_h2(a0, a1);
    }
}

// ---- main GEMM --------------------------------------------------------------

template <int EPI>
__global__ void __launch_bounds__(NT, 2)
ngemm_kernel(const unsigned short* __restrict__ Ax,
             const unsigned short* __restrict__ Bx,
             const float* __restrict__ bias,
             const float* __restrict__ trow, float tval,
             const float* __restrict__ bw31,
             unsigned short* __restrict__ oh,
             float* __restrict__ hw1,
             const float* __restrict__ hbase,
             const unsigned short* __restrict__ ysum,
             unsigned short* __restrict__ Sbuf,
             float* __restrict__ hout, float coef, float kc,
             const int* flag_in, int* flag_out) {
    extern __shared__ char smc[];
    const uint32_t sb = smem_to_u32(smc);
    const int tid = threadIdx.x;
    const int lane = tid & 31;
    const int w = tid >> 5;
    const int wm = w & 1;
    const int wn = w >> 1;
    const int bm = blockIdx.y * BM;
    const int bn = blockIdx.x * BN;

    const int cr = tid >> 3;
    const int cc = (tid & 7) * 8;
    const unsigned short* gaP[4];
    const unsigned short* gbP[4];
    uint32_t scP[4];
#pragma unroll
    for (int k = 0; k < 4; ++k) {
        const int row = k * 32 + cr;
        gaP[k] = Ax + (size_t)(bm + row) * KDIM + cc;
        gbP[k] = Bx + (size_t)(bn + row) * KDIM + cc;
        scP[k] = (uint32_t)(row * RSB + (tid & 7) * 16);
    }

    const uint32_t a_off = (uint32_t)((lane & 15) * RSB + ((lane & 16) ? 16 : 0));
    const uint32_t b_off = (uint32_t)(((lane & 7) + ((lane & 16) ? 8 : 0)) * RSB +
                                      ((lane & 8) ? 16 : 0));

    float acc[4][4][4];
#pragma unroll
    for (int i = 0; i < 4; i++)
#pragma unroll
        for (int j = 0; j < 4; j++)
#pragma unroll
            for (int q = 0; q < 4; q++) acc[i][j][q] = 0.f;

    // ---- B (weights) prefetch for stages 0,1: no data dependency.
#pragma unroll
    for (int k = 0; k < 4; ++k) {
        CP_ASYNC16(sb + 0 * STAGE_B + T_B + scP[k], gbP[k]);
        CP_ASYNC16(sb + 1 * STAGE_B + T_B + scP[k], gbP[k] + BK);
    }

    if (EPI != EPI_STORE) {
        GRIDDEP_LAUNCH();  // successors self-protect via rowblock flags
        if (flag_in != nullptr) {
            if (tid == 0) {
                volatile int* fi = (volatile int*)(flag_in + blockIdx.y);
                while (*fi < NPROD) __nanosleep(64);
                __threadfence();  // acquire
                int old = atomicAdd((int*)(flag_in + blockIdx.y), 1);
                if (old == 2 * NPROD - 1)
                    atomicExch((int*)(flag_in + blockIdx.y), 0);
            }
            __syncthreads();
        } else {
            GRIDDEP_WAIT();  // first chain kernel: wait for prep kernels
        }
    }

    // A prologue loads. Groups: g0 = {8x B prefetch, A0}, g1 = {A1}.
#pragma unroll
    for (int k = 0; k < 4; ++k)
        CP_ASYNC16(sb + 0 * STAGE_B + T_A + scP[k], gaP[k]);
    CP_COMMIT();
#pragma unroll
    for (int k = 0; k < 4; ++k)
        CP_ASYNC16(sb + 1 * STAGE_B + T_A + scP[k], gaP[k] + BK);
    CP_COMMIT();

#define ISSUE_STAGE(st)                                                   \
    do {                                                                  \
        const int _kc = (st) * BK;                                        \
        const uint32_t _b = sb + ((st) % NBUF) * STAGE_B;                 \
        _Pragma("unroll")                                                 \
        for (int _k = 0; _k < 4; ++_k) {                                  \
            CP_ASYNC16(_b + T_A + scP[_k], gaP[_k] + _kc);                \
            CP_ASYNC16(_b + T_B + scP[_k], gbP[_k] + _kc);                \
        }                                                                 \
        CP_COMMIT();                                                      \
    } while (0)

#pragma unroll 1
    for (int s = 0; s < NSTAGES; ++s) {
        if (s + 1 < NSTAGES) {
            CP_WAIT1();
        } else {
            CP_WAIT0();
        }
        __syncthreads();
        if (s + 2 < NSTAGES) ISSUE_STAGE(s + 2);

        const uint32_t base = sb + (s % NBUF) * STAGE_B;
#pragma unroll
        for (int ks = 0; ks < 4; ++ks) {
            uint32_t a_[4][4], b_[4][2];
#pragma unroll
            for (int i = 0; i < 4; ++i) {
                const uint32_t ra =
                    base + (uint32_t)((wm * 64 + i * 16) * RSB + ks * 32) + a_off;
                LDSM_X4(a_[i][0], a_[i][1], a_[i][2], a_[i][3], ra + T_A);
            }
#pragma unroll
            for (int jj = 0; jj < 2; ++jj) {
                const uint32_t rb =
                    base + (uint32_t)((wn * 32 + jj * 16) * RSB + ks * 32) + b_off;
                uint32_t t0, t1, t2, t3;
                LDSM_X4(t0, t1, t2, t3, rb + T_B);
                b_[2 * jj][0] = t0; b_[2 * jj][1] = t1;
                b_[2 * jj + 1][0] = t2; b_[2 * jj + 1][1] = t3;
            }
#pragma unroll
            for (int i = 0; i < 4; ++i)
#pragma unroll
                for (int j = 0; j < 4; ++j) {
                    MMA_F16(acc[i][j], a_[i], b_[j]);
                }
        }
    }
#undef ISSUE_STAGE

    // ---------------- epilogue -------------------------------------------
#pragma unroll
    for (int j = 0; j < 4; ++j) {
        const int c = bn + wn * 32 + j * 8 + (lane & 3) * 2;
        float bb0 = 0.f, bb1 = 0.f, cc0 = 0.f, cc1 = 0.f;
        if (EPI != EPI_STORE) {
            bb0 = bias[c];
            bb1 = bias[c + 1];
        }
        if (EPI == EPI_FINAL) {
            bb0 *= kc;  // kc = 10*dt = 1.0
            bb1 *= kc;
        }
        if (EPI == EPI_HW1 || EPI == EPI_L1MID || EPI == EPI_STEPEND) {
            if (trow != nullptr) {
                bb0 = fmaf(tval, trow[c], bb0);
                bb1 = fmaf(tval, trow[c + 1], bb1);
            }
        }
        if (EPI == EPI_L1MID) {
            bb0 = fmaf(coef, bw31[c], bb0);
            bb1 = fmaf(coef, bw31[c + 1], bb1);
        }
        if (EPI == EPI_STEPEND) {
            cc0 = 0.1f * bw31[c];      // dt * bW31
            cc1 = 0.1f * bw31[c + 1];
        }
#pragma unroll
        for (int i = 0; i < 4; ++i) {
            const int m0 = bm + wm * 64 + i * 16 + (lane >> 2);
            epi_rc<EPI>(m0, c, acc[i][j][0], acc[i][j][1], bb0, bb1, cc0, cc1,
                        oh, hw1, hbase, ysum, Sbuf, hout, coef, kc);
            epi_rc<EPI>(m0 + 8, c, acc[i][j][2], acc[i][j][3], bb0, bb1,
                        cc0, cc1, oh, hw1, hbase, ysum, Sbuf, hout, coef, kc);
        }
    }

    if (EPI != EPI_STORE && flag_out != nullptr) {
        __syncthreads();
        if (tid == 0) {
            __threadfence();  // release
            atomicAdd(flag_out + blockIdx.y, 1);
        }
    }
}

// ---------------------------------------------------------------------------

template <int EPI>
static inline void launch_gemm(const unsigned short* Ax, const unsigned short* Bx,
                               const float* bias, const float* trow, float tval,
                               const float* bw31, unsigned short* oh,
                               float* hw1, const float* hbase,
                               const unsigned short* ysum,
                               unsigned short* Sbuf, float* hout,
                               float coef, float kc,
                               const int* flag_in, int* flag_out) {
    cudaLaunchConfig_t cfg = {};
    cfg.gridDim = dim3(NDIM / BN, MDIM / BM);
    cfg.blockDim = dim3(NT);
    cfg.dynamicSmemBytes = SMEM_TOTAL;
    cfg.stream = 0;
    cudaLaunchAttribute attr[1];
    attr[0].id = cudaLaunchAttributeProgrammaticStreamSerialization;
    attr[0].val.programmaticStreamSerializationAllowed = 1;
    cfg.attrs = attr;
    cfg.numAttrs = 1;
    cudaLaunchKernelEx(&cfg, ngemm_kernel<EPI>, Ax, Bx, bias, trow, tval,
                       bw31, oh, hw1, hbase, ysum, Sbuf, hout, coef, kc,
                       flag_in, flag_out);
}

extern "C" void kernel_launch(void* const* d_in, const int* in_sizes, int n_in,
                              void* d_out, int out_size) {
    const float* h0 = (const float*)d_in[0];
    const float* W1 = (const float*)d_in[1];
    const float* b1 = (const float*)d_in[2];
    const float* W2 = (const float*)d_in[3];
    const float* b2 = (const float*)d_in[4];
    const float* W3 = (const float*)d_in[5];
    const float* b3 = (const float*)d_in[6];
    float* out = (float*)d_out;

    cudaFuncSetAttribute(ngemm_kernel<EPI_HW1>,
                         cudaFuncAttributeMaxDynamicSharedMemorySize, SMEM_TOTAL);
    cudaFuncSetAttribute(ngemm_kernel<EPI_L2>,
                         cudaFuncAttributeMaxDynamicSharedMemorySize, SMEM_TOTAL);
    cudaFuncSetAttribute(ngemm_kernel<EPI_L1MID>,
                         cudaFuncAttributeMaxDynamicSharedMemorySize, SMEM_TOTAL);
    cudaFuncSetAttribute(ngemm_kernel<EPI_STEPEND>,
                         cudaFuncAttributeMaxDynamicSharedMemorySize, SMEM_TOTAL);
    cudaFuncSetAttribute(ngemm_kernel<EPI_FINAL>,
                         cudaFuncAttributeMaxDynamicSharedMemorySize, SMEM_TOTAL);
    cudaFuncSetAttribute(ngemm_kernel<EPI_STORE>,
                         cudaFuncAttributeMaxDynamicSharedMemorySize, SMEM_TOTAL);

    float* fbase = nullptr;
    cudaGetSymbolAddress((void**)&fbase, g_f32);
    unsigned short* abase = nullptr;
    cudaGetSymbolAddress((void**)&abase, g_bf);
    unsigned short* wbase = nullptr;
    cudaGetSymbolAddress((void**)&wbase, g_wt);
    float* vbase = nullptr;
    cudaGetSymbolAddress((void**)&vbase, g_vec);
    int* flbase = nullptr;
    cudaGetSymbolAddress((void**)&flbase, g_flags);

    const size_t SZ = (size_t)MDIM * NDIM;
    float* hw1 = fbase;                     // carried fp32 h@W1'

    unsigned short* hs = abase;             // fp16(h0), prologue A operand
    unsigned short* y1 = abase + SZ;
    unsigned short* y2 = abase + 2 * SZ;
    unsigned short* ys = abase + 3 * SZ;    // ysum (per-step RK weights)
    unsigned short* Sb = abase + 4 * SZ;    // S = sum over steps of ysum

    const size_t WSZ = (size_t)KDIM * NDIM;
    unsigned short* w1x = wbase;
    unsigned short* w2x = wbase + WSZ;
    unsigned short* w3x = wbase + 2 * WSZ;
    unsigned short* w31x = wbase + 3 * WSZ;
    unsigned short* w3row = wbase + 4 * WSZ;  // fp16(W3) row-major
    float* bw31 = vbase;

    // ---- one-time prep ----------------------------------------------------
    {
        dim3 g(NDIM / 32, KDIM / 32), b(32, 8);
        wsplit_kernel<<<g, b>>>(W1, w1x);
        wsplit_kernel<<<g, b>>>(W2, w2x);
        wsplit_kernel<<<g, b>>>(W3, w3x);
        asplit_kernel<<<(int)(SZ / 4 / 256), 256>>>(h0, hs);
        asplit_kernel<<<(int)(WSZ / 4 / 256), 256>>>(W3, w3row);
        bw31_kernel<<<NDIM / 256, 256>>>(b3, W1, bw31);
        // W31^T[n][i] = sum_j W1[j][n]*W3[i][j] (plain launch, no PDL)
        ngemm_kernel<EPI_STORE><<<dim3(NDIM / BN, NDIM / BM), NT, SMEM_TOTAL>>>(
            w1x, w3row, nullptr, nullptr, 0.f, nullptr, w31x, nullptr,
            nullptr, nullptr, nullptr, nullptr, 0.f, 0.f, nullptr, nullptr);
    }

    const float dt = 0.1f;
    const float* trow = W1 + (size_t)KDIM * NDIM;  // W1 row 1024 (t row)

    int edge = 0;
#define FLAG_IN  ((edge == 0) ? (const int*)nullptr : (const int*)(flbase + (edge - 1) * NRB))
#define FLAG_OUT ((edge < NEDGES - 1) ? (flbase + edge * NRB) : (int*)nullptr)

    // Prologue: hW1 = h0@W1' (fp32); y1 = tanh(hW1 + b1 + 0*trow)
    launch_gemm<EPI_HW1>(hs, w1x, b1, trow, 0.f, nullptr, y1, hw1,
                         nullptr, nullptr, nullptr, nullptr, 0.f, 0.f,
                         FLAG_IN, FLAG_OUT); edge++;

    for (int s = 0; s < STEPS_N; s++) {
        const float t0 = dt * (float)s;
        const float tn = dt * (float)(s + 1);

        // y2_1 ; ysum = y2_1
        launch_gemm<EPI_L2>(y1, w2x, b2, nullptr, 0.f, nullptr, y2, nullptr,
                            nullptr, nullptr, ys, nullptr, 0.f, 0.f,
                            FLAG_IN, FLAG_OUT); edge++;
        // eval2 layer1 (coef dt/2)
        launch_gemm<EPI_L1MID>(y2, w31x, b1, trow, t0 + dt * 0.5f, bw31, y1,
                               hw1, nullptr, nullptr, nullptr, nullptr,
                               dt * 0.5f, 0.f, FLAG_IN, FLAG_OUT); edge++;
        // y2_2 ; ysum += 2*y2_2
        launch_gemm<EPI_L2>(y1, w2x, b2, nullptr, 0.f, nullptr, y2, nullptr,
                            nullptr, nullptr, ys, nullptr, 0.f, 2.f,
                            FLAG_IN, FLAG_OUT); edge++;
        // eval3 layer1 (coef dt/2)
        launch_gemm<EPI_L1MID>(y2, w31x, b1, trow, t0 + dt * 0.5f, bw31, y1,
                               hw1, nullptr, nullptr, nullptr, nullptr,
                               dt * 0.5f, 0.f, FLAG_IN, FLAG_OUT); edge++;
        // y2_3 ; ysum += 2*y2_3
        launch_gemm<EPI_L2>(y1, w2x, b2, nullptr, 0.f, nullptr, y2, nullptr,
                            nullptr, nullptr, ys, nullptr, 0.f, 2.f,
                            FLAG_IN, FLAG_OUT); edge++;
        // eval4 layer1 (coef dt)
        launch_gemm<EPI_L1MID>(y2, w31x, b1, trow, t0 + dt, bw31, y1,
                               hw1, nullptr, nullptr, nullptr, nullptr,
                               dt, 0.f, FLAG_IN, FLAG_OUT); edge++;
        // y2_4 ; ysum += y2_4
        launch_gemm<EPI_L2>(y1, w2x, b2, nullptr, 0.f, nullptr, y2, nullptr,
                            nullptr, nullptr, ys, nullptr, 0.f, 1.f,
                            FLAG_IN, FLAG_OUT); edge++;
        // STEPEND: hW1 += dt/6*(ysum@W31) + dt*bW31; S += ysum;
        //          y1 = tanh(hW1' + b1 + tn*trow)
        launch_gemm<EPI_STEPEND>(ys, w31x, b1, trow, tn, bw31, y1,
                                 hw1, nullptr, ys, Sb, nullptr,
                                 dt / 6.0f, (s == 0) ? 0.f : 1.f,
                                 FLAG_IN, FLAG_OUT); edge++;
    }

    // FINAL: out = h0 + dt/6*(S@W3) + 10*dt*b3  (10*dt = 1.0)
    launch_gemm<EPI_FINAL>(Sb, w3x, b3, nullptr, 0.f, nullptr, nullptr,
                           nullptr, h0, nullptr, nullptr, out,
                           dt / 6.0f, 1.0f, FLAG_IN, FLAG_OUT); edge++;
#undef FLAG_IN
#undef FLAG_OUT
}